// round 9
// baseline (speedup 1.0000x reference)
#include <cuda_runtime.h>
#include <cuda_bf16.h>
#include <math_constants.h>
#include <cstdint>

#define Bn 4
#define Tn 2048
#define Cn 1024
#define Hn 16
#define Dn 64
#define BT (Bn*Tn)      // 8192
#define NQT (Tn/128)    // 16 q-tiles of 128

typedef unsigned short ushort_t;

// Scratch (device globals — no allocation allowed)
__device__ __align__(16) ushort_t g_qh[(size_t)64*Tn*Dn];   // bf16 hi/lo of q (pre-scaled 0.125)
__device__ __align__(16) ushort_t g_ql[(size_t)64*Tn*Dn];
__device__ __align__(16) ushort_t g_kh[(size_t)64*Tn*Dn];
__device__ __align__(16) ushort_t g_kl[(size_t)64*Tn*Dn];
__device__ __align__(16) ushort_t g_vh[(size_t)64*Tn*Dn];
__device__ __align__(16) ushort_t g_vl[(size_t)64*Tn*Dn];
__device__ __align__(16) ushort_t g_xh[(size_t)BT*Cn];      // x pre-split
__device__ __align__(16) ushort_t g_xl[(size_t)BT*Cn];
__device__ __align__(16) ushort_t g_wh[(size_t)4*Cn*Cn];    // Wq,Wk,Wv,Wp pre-split
__device__ __align__(16) ushort_t g_wl[(size_t)4*Cn*Cn];
__device__ __align__(16) ushort_t g_yh[(size_t)BT*Cn];      // attention out (normalized), pre-split
__device__ __align__(16) ushort_t g_yl[(size_t)BT*Cn];
__device__ float g_lsum[(size_t)64*Tn];                     // softmax row sums

// ---------------------------------------------------------------------------
// helpers
// ---------------------------------------------------------------------------
__device__ __forceinline__ uint32_t smem_u32(const void* p) {
    uint32_t a;
    asm("{ .reg .u64 t; cvta.to.shared.u64 t, %1; cvt.u32.u64 %0, t; }"
        : "=r"(a) : "l"(p));
    return a;
}

__device__ __forceinline__ void split2(float f0, float f1, uint32_t& hi, uint32_t& lo) {
    __nv_bfloat16 h0 = __float2bfloat16(f0);
    __nv_bfloat16 h1 = __float2bfloat16(f1);
    __nv_bfloat16 l0 = __float2bfloat16(f0 - __bfloat162float(h0));
    __nv_bfloat16 l1 = __float2bfloat16(f1 - __bfloat162float(h1));
    hi = (uint32_t)__bfloat16_as_ushort(h0) | ((uint32_t)__bfloat16_as_ushort(h1) << 16);
    lo = (uint32_t)__bfloat16_as_ushort(l0) | ((uint32_t)__bfloat16_as_ushort(l1) << 16);
}

__device__ __forceinline__ void ldm_x4(uint32_t r[4], uint32_t addr) {
    asm volatile("ldmatrix.sync.aligned.m8n8.x4.shared.b16 {%0,%1,%2,%3}, [%4];"
        : "=r"(r[0]), "=r"(r[1]), "=r"(r[2]), "=r"(r[3]) : "r"(addr));
}

__device__ __forceinline__ void ldm_x4_t(uint32_t r[4], uint32_t addr) {
    asm volatile("ldmatrix.sync.aligned.m8n8.x4.trans.shared.b16 {%0,%1,%2,%3}, [%4];"
        : "=r"(r[0]), "=r"(r[1]), "=r"(r[2]), "=r"(r[3]) : "r"(addr));
}

__device__ __forceinline__ void mma_bf16(float d[4], const uint32_t a[4], const uint32_t b[2]) {
    asm volatile(
        "mma.sync.aligned.m16n8k16.row.col.f32.bf16.bf16.f32 "
        "{%0,%1,%2,%3}, {%4,%5,%6,%7}, {%8,%9}, {%0,%1,%2,%3};"
        : "+f"(d[0]), "+f"(d[1]), "+f"(d[2]), "+f"(d[3])
        : "r"(a[0]), "r"(a[1]), "r"(a[2]), "r"(a[3]), "r"(b[0]), "r"(b[1]));
}

#define CP16(dst, src) asm volatile("cp.async.cg.shared.global [%0], [%1], 16;" :: "r"(dst), "l"(src))
#define CPCOMMIT()     asm volatile("cp.async.commit_group;" ::: "memory")
#define CPWAIT0()      asm volatile("cp.async.wait_group 0;" ::: "memory")
#define CPWAIT1()      asm volatile("cp.async.wait_group 1;" ::: "memory")

// ---------------------------------------------------------------------------
// combined pre-convert kernel: fp32 -> bf16 hi/lo for x and all 4 weights
// ---------------------------------------------------------------------------
__global__ __launch_bounds__(256) void conv_all(
    const float4* __restrict__ x,
    const float4* __restrict__ Wq, const float4* __restrict__ Wk,
    const float4* __restrict__ Wv, const float4* __restrict__ Wp)
{
    int b = blockIdx.x;
    const float4* src;
    uint2 *dh, *dl;
    int i;
    if (b < 8192) {               // x: 2M float4
        i = b * 256 + threadIdx.x;
        src = x; dh = (uint2*)g_xh; dl = (uint2*)g_xl;
    } else {                      // weights: 4 x 256K float4
        b -= 8192;
        const int z = b >> 10;
        src = (z == 0) ? Wq : (z == 1) ? Wk : (z == 2) ? Wv : Wp;
        dh = (uint2*)(g_wh + (size_t)z * Cn * Cn);
        dl = (uint2*)(g_wl + (size_t)z * Cn * Cn);
        i = (b & 1023) * 256 + threadIdx.x;
    }
    float4 v = src[i];
    uint32_t h0, l0, h1, l1;
    split2(v.x, v.y, h0, l0);
    split2(v.z, v.w, h1, l1);
    dh[i] = make_uint2(h0, h1);
    dl[i] = make_uint2(l0, l1);
}

// ===========================================================================
// bf16 pre-split GEMM, cp.async 3-stage, CTA 128x128, warp tile 64x32
// (8 warps: 2m x 4n), ~120 regs -> 2 CTAs/SM.
// Stage: Ah@0 (128x80B), Al@10240, Bh@20480 (32x272B), Bl@29184 => 37888 B.
// ===========================================================================
#define GSTG 37888
#define GEMM_SMEM (3*GSTG)   // 113664

__device__ __forceinline__ void gemm_issue(
    uint32_t sbase,
    const ushort_t* __restrict__ Ah_g, const ushort_t* __restrict__ Al_g,
    const ushort_t* __restrict__ Bh_g, const ushort_t* __restrict__ Bl_g,
    int bm, int bn, int kc, int tid)
{
    #pragma unroll
    for (int i = 0; i < 2; i++) {
        const int ia = tid + 256 * i;
        const int r = ia >> 2, c = ia & 3;
        const uint32_t dst = sbase + (uint32_t)(r * 80 + c * 16);
        const size_t src = (size_t)(bm * 128 + r) * 1024 + kc * 32 + c * 8;
        CP16(dst, Ah_g + src);
        CP16(dst + 10240, Al_g + src);
    }
    #pragma unroll
    for (int i = 0; i < 2; i++) {
        const int ib = tid + 256 * i;
        const int k = ib >> 4, c = ib & 15;
        const uint32_t dst = sbase + (uint32_t)(20480 + k * 272 + c * 16);
        const size_t src = (size_t)(kc * 32 + k) * 1024 + bn * 128 + c * 8;
        CP16(dst, Bh_g + src);
        CP16(dst + 8704, Bl_g + src);
    }
    CPCOMMIT();
}

template<bool REMAP>
__device__ __forceinline__ void gemm2_body(
    const ushort_t* __restrict__ Ah_g, const ushort_t* __restrict__ Al_g,
    const ushort_t* __restrict__ Bh_g, const ushort_t* __restrict__ Bl_g,
    const float* __restrict__ bias, float* __restrict__ out,
    ushort_t* __restrict__ outH, ushort_t* __restrict__ outL, float scl,
    int bm, int bn)
{
    extern __shared__ char smc[];
    const uint32_t sb = smem_u32(smc);
    const int tid = threadIdx.x, wid = tid >> 5, lane = tid & 31;
    const int warp_m = wid & 1;        // 64 rows each
    const int warp_n = wid >> 1;       // 32 cols each

    const int l15 = lane & 15;
    const int lhi = lane >> 4;
    const uint32_t aBase = sb + (uint32_t)((warp_m * 64 + l15) * 80 + lhi * 16);
    const uint32_t bBase = sb + 20480 + (uint32_t)(l15 * 272 + warp_n * 64 + lhi * 16);

    float d[4][4][4];
    #pragma unroll
    for (int t = 0; t < 4; t++)
        #pragma unroll
        for (int u = 0; u < 4; u++)
            #pragma unroll
            for (int v = 0; v < 4; v++) d[t][u][v] = 0.f;

    gemm_issue(sb,        Ah_g, Al_g, Bh_g, Bl_g, bm, bn, 0, tid);
    gemm_issue(sb + GSTG, Ah_g, Al_g, Bh_g, Bl_g, bm, bn, 1, tid);

    for (int kc = 0; kc < 32; kc++) {
        if (kc == 31) { CPWAIT0(); } else { CPWAIT1(); }
        __syncthreads();
        if (kc < 30)
            gemm_issue(sb + (uint32_t)(((kc + 2) % 3) * GSTG),
                       Ah_g, Al_g, Bh_g, Bl_g, bm, bn, kc + 2, tid);

        const uint32_t stgOff = (uint32_t)((kc % 3) * GSTG);

        #pragma unroll
        for (int ss = 0; ss < 2; ss++) {
            uint32_t Bh[4][2], Bl[4][2];
            #pragma unroll
            for (int gp = 0; gp < 2; gp++) {
                const uint32_t ba = bBase + stgOff + (uint32_t)(ss * 16 * 272 + gp * 32);
                uint32_t r[4];
                ldm_x4_t(r, ba);
                Bh[gp*2][0] = r[0]; Bh[gp*2][1] = r[1];
                Bh[gp*2+1][0] = r[2]; Bh[gp*2+1][1] = r[3];
                ldm_x4_t(r, ba + 8704);
                Bl[gp*2][0] = r[0]; Bl[gp*2][1] = r[1];
                Bl[gp*2+1][0] = r[2]; Bl[gp*2+1][1] = r[3];
            }
            #pragma unroll
            for (int t = 0; t < 4; t++) {
                uint32_t Ah[4], Al_[4];
                const uint32_t aa = aBase + stgOff + (uint32_t)(t * 16 * 80 + ss * 32);
                ldm_x4(Ah, aa);
                ldm_x4(Al_, aa + 10240);
                #pragma unroll
                for (int u = 0; u < 4; u++) {
                    mma_bf16(d[t][u], Ah, Bh[u]);
                    mma_bf16(d[t][u], Ah, Bl[u]);
                    mma_bf16(d[t][u], Al_, Bh[u]);
                }
            }
        }
    }

    // ---- epilogue ----
    #pragma unroll
    for (int t = 0; t < 4; t++) {
        const int rowA = bm * 128 + warp_m * 64 + t * 16 + (lane >> 2);
        #pragma unroll
        for (int half = 0; half < 2; half++) {
            const int m = rowA + half * 8;
            #pragma unroll
            for (int u = 0; u < 4; u++) {
                const int col = bn * 128 + warp_n * 32 + u * 8 + ((lane & 3) << 1);
                const float v0 = d[t][u][half * 2 + 0] + __ldg(&bias[col]);
                const float v1 = d[t][u][half * 2 + 1] + __ldg(&bias[col + 1]);
                if (REMAP) {
                    const int b = m >> 11, tt = m & 2047;
                    const int h = col >> 6, d0 = col & 63;
                    const size_t idx = (((size_t)(b * Hn + h) * Tn) + tt) * Dn + d0;
                    uint32_t hh, ll;
                    split2(v0 * scl, v1 * scl, hh, ll);
                    *(uint32_t*)(outH + idx) = hh;
                    *(uint32_t*)(outL + idx) = ll;
                } else {
                    *(float2*)(out + (size_t)m * 1024 + col) = make_float2(v0, v1);
                }
            }
        }
    }
}

__global__ __launch_bounds__(256, 2) void gemm_qkv_tc(
    const float* __restrict__ bq, const float* __restrict__ bk,
    const float* __restrict__ bv)
{
    const float* bias; ushort_t *oh, *ol; float scl;
    if (blockIdx.z == 0)      { bias = bq; oh = g_qh; ol = g_ql; scl = 0.125f; }
    else if (blockIdx.z == 1) { bias = bk; oh = g_kh; ol = g_kl; scl = 1.f; }
    else                      { bias = bv; oh = g_vh; ol = g_vl; scl = 1.f; }
    const size_t wo = (size_t)blockIdx.z * Cn * Cn;
    gemm2_body<true>(g_xh, g_xl, g_wh + wo, g_wl + wo, bias, nullptr, oh, ol, scl,
                     blockIdx.y, blockIdx.x);
}

// ---------------------------------------------------------------------------
// Output projection + att normalization, CTA-specialized in one launch:
//   by <  16 : norm CTAs (128 total, scheduled first -> wave-1 residency)
//   by >= 16 : GEMM CTAs (512, the proven 128x128 proj GEMM)
// ---------------------------------------------------------------------------
__global__ __launch_bounds__(256, 2) void gemm_proj_tc(
    const float* __restrict__ bp, float* __restrict__ out,
    float* __restrict__ att)
{
    if (blockIdx.y < 16) {
        // -------- norm CTAs: 128 CTAs x 8 warps, 128 rows per warp --------
        const int wid = threadIdx.x >> 5, lane = threadIdx.x & 31;
        const int cta = blockIdx.y * 8 + blockIdx.x;       // 0..127
        const int row0 = cta * 1024 + wid * 128;
        #pragma unroll 1
        for (int i = 0; i < 128; i++) {
            const int row = row0 + i;
            const int rs = row & (Tn - 1);
            const int width = ((rs >> 7) + 1) * 128;
            const float inv = 1.f / g_lsum[row];
            float* p = att + (size_t)row * Tn;
            for (int c = lane * 4; c < width; c += 128) {
                float4 v = *(float4*)(p + c);
                v.x *= inv; v.y *= inv; v.z *= inv; v.w *= inv;
                *(float4*)(p + c) = v;
            }
        }
        return;
    }
    // -------- GEMM CTAs --------
    const size_t wo = (size_t)3 * Cn * Cn;
    gemm2_body<false>(g_yh, g_yl, g_wh + wo, g_wl + wo, bp, out,
                      nullptr, nullptr, 1.f, blockIdx.y - 16, blockIdx.x);
}

// ===========================================================================
// MMA attention (R8, unchanged): single pass, unnormalized E -> att,
// y = E@V / l written as bf16 hi/lo.
// ===========================================================================
#define ATT_SMEM 131072
#define AKH 0
#define AKL 16384
#define AVH 32768
#define AVL 49152

__global__ __launch_bounds__(256, 1) void attn_mma(float* __restrict__ att)
{
    extern __shared__ char smc[];
    const uint32_t sb = smem_u32(smc);
    const int tid = threadIdx.x, wid = tid >> 5, lane = tid & 31;
    const int bh = blockIdx.y;
    const int qt = (NQT - 1) - blockIdx.x;
    const int qbase = qt * 128;
    const int nkt = qt + 1;

    const ushort_t* qh = g_qh + ((size_t)bh * Tn + qbase) * Dn;
    const ushort_t* ql = g_ql + ((size_t)bh * Tn + qbase) * Dn;
    const ushort_t* khp = g_kh + (size_t)bh * Tn * Dn;
    const ushort_t* klp = g_kl + (size_t)bh * Tn * Dn;
    const ushort_t* vhp = g_vh + (size_t)bh * Tn * Dn;
    const ushort_t* vlp = g_vl + (size_t)bh * Tn * Dn;
    float* attp = att + ((size_t)bh * Tn + qbase) * Tn;

    // Q stage into buffer0
    #pragma unroll
    for (int i = 0; i < 4; i++) {
        const int idx = tid + 256 * i;
        const int r = idx >> 3, c = idx & 7;
        const uint32_t off = (uint32_t)(r * 128 + ((c ^ (r & 7)) << 4));
        CP16(sb + AKH + off, qh + r * 64 + c * 8);
        CP16(sb + AKL + off, ql + r * 64 + c * 8);
    }
    CPCOMMIT();

    // K/V tile 0 into buffer1
    {
        const uint32_t base = sb + 65536;
        #pragma unroll
        for (int i = 0; i < 4; i++) {
            const int idx = tid + 256 * i;
            const int r = idx >> 3, c = idx & 7;
            const uint32_t off = (uint32_t)(r * 128 + ((c ^ (r & 7)) << 4));
            const size_t so = (size_t)r * 64 + c * 8;
            CP16(base + AKH + off, khp + so);
            CP16(base + AKL + off, klp + so);
            CP16(base + AVH + off, vhp + so);
            CP16(base + AVL + off, vlp + so);
        }
        CPCOMMIT();
    }

    // zero-fill strict-upper tiles while the async loads fly
    const int zstart = nkt * 128;
    #pragma unroll 1
    for (int rg = 0; rg < 16; rg++) {
        const int r = rg * 8 + wid;
        for (int c = zstart + lane * 4; c < Tn; c += 128)
            *(float4*)(attp + (size_t)r * Tn + c) = make_float4(0.f, 0.f, 0.f, 0.f);
    }

    CPWAIT1();
    __syncthreads();

    uint32_t q_h[4][4], q_l[4][4];
    {
        const int arow = 16 * wid + ((lane >> 3) & 1) * 8 + (lane & 7);
        #pragma unroll
        for (int kk = 0; kk < 4; kk++) {
            const uint32_t addr = sb + AKH + (uint32_t)(arow * 128 +
                (((2 * kk + (lane >> 4)) ^ (arow & 7)) << 4));
            ldm_x4(q_h[kk], addr);
            ldm_x4(q_l[kk], addr + 16384);
        }
    }
    __syncthreads();

    const int bkeyL = ((lane >> 4) << 3) + (lane & 7);
    const int bchk  = (lane >> 3) & 1;
    const uint32_t brow = (uint32_t)(bkeyL * 128);
    const int bsw = bkeyL & 7;

    const int vkeyL = ((lane >> 3) & 1) * 8 + (lane & 7);
    const int vchk  = lane >> 4;
    const uint32_t vrow = (uint32_t)(vkeyL * 128);
    const int vsw = vkeyL & 7;

    const int rl0 = 16 * wid + (lane >> 2);
    const int cl0 = 2 * (lane & 3);

    float d_y[8][4];
    #pragma unroll
    for (int j = 0; j < 8; j++)
        #pragma unroll
        for (int v = 0; v < 4; v++) d_y[j][v] = 0.f;
    float lsum0 = 0.f, lsum1 = 0.f;

    for (int kt = 0; kt < nkt; kt++) {
        const int buf = (kt + 1) & 1;
        if (kt + 1 < nkt) {
            const uint32_t base = sb + (uint32_t)((kt & 1) * 65536);
            const size_t tof = (size_t)(kt + 1) * 128 * 64;
            #pragma unroll
            for (int i = 0; i < 4; i++) {
                const int idx = tid + 256 * i;
                const int r = idx >> 3, c = idx & 7;
                const uint32_t off = (uint32_t)(r * 128 + ((c ^ (r & 7)) << 4));
                const size_t so = tof + (size_t)r * 64 + c * 8;
                CP16(base + AKH + off, khp + so);
                CP16(base + AKL + off, klp + so);
                CP16(base + AVH + off, vhp + so);
                CP16(base + AVL + off, vlp + so);
            }
            CPCOMMIT();
            CPWAIT1();
        } else {
            CPWAIT0();
        }
        __syncthreads();

        const uint32_t base = sb + (uint32_t)(buf * 65536);

        float ds[16][4];
        #pragma unroll
        for (int j = 0; j < 16; j++)
            #pragma unroll
            for (int v = 0; v < 4; v++) ds[j][v] = 0.f;

        #pragma unroll
        for (int kk = 0; kk < 4; kk++) {
            #pragma unroll
            for (int j16 = 0; j16 < 8; j16++) {
                const uint32_t ka = base + AKH + (uint32_t)(j16 * 2048) + brow +
                                    (uint32_t)((((kk << 1) | bchk) ^ bsw) << 4);
                uint32_t khf[4], klf[4];
                ldm_x4(khf, ka);
                ldm_x4(klf, ka + 16384);
                uint32_t b0h[2] = {khf[0], khf[1]}, b1h[2] = {khf[2], khf[3]};
                uint32_t b0l[2] = {klf[0], klf[1]}, b1l[2] = {klf[2], klf[3]};
                mma_bf16(ds[2*j16],   q_h[kk], b0h);
                mma_bf16(ds[2*j16],   q_h[kk], b0l);
                mma_bf16(ds[2*j16],   q_l[kk], b0h);
                mma_bf16(ds[2*j16+1], q_h[kk], b1h);
                mma_bf16(ds[2*j16+1], q_h[kk], b1l);
                mma_bf16(ds[2*j16+1], q_l[kk], b1h);
            }
        }

        const bool diag = (kt == qt);
        const int ktbase = kt * 128;
        #pragma unroll
        for (int j = 0; j < 16; j++) {
            const int c = 8 * j + cl0;
            float e00 = __expf(ds[j][0]);
            float e01 = __expf(ds[j][1]);
            float e10 = __expf(ds[j][2]);
            float e11 = __expf(ds[j][3]);
            if (diag) {
                if (c     > rl0)     e00 = 0.f;
                if (c + 1 > rl0)     e01 = 0.f;
                if (c     > rl0 + 8) e10 = 0.f;
                if (c + 1 > rl0 + 8) e11 = 0.f;
            }
            ds[j][0] = e00; ds[j][1] = e01; ds[j][2] = e10; ds[j][3] = e11;
            *(float2*)(attp + (size_t)rl0 * Tn + ktbase + c)       = make_float2(e00, e01);
            *(float2*)(attp + (size_t)(rl0 + 8) * Tn + ktbase + c) = make_float2(e10, e11);
            lsum0 += e00 + e01;
            lsum1 += e10 + e11;
        }

        #pragma unroll
        for (int kap = 0; kap < 8; kap++) {
            uint32_t p_h[4], p_l[4];
            split2(ds[2*kap][0],   ds[2*kap][1],   p_h[0], p_l[0]);
            split2(ds[2*kap][2],   ds[2*kap][3],   p_h[1], p_l[1]);
            split2(ds[2*kap+1][0], ds[2*kap+1][1], p_h[2], p_l[2]);
            split2(ds[2*kap+1][2], ds[2*kap+1][3], p_h[3], p_l[3]);
            #pragma unroll
            for (int j16 = 0; j16 < 4; j16++) {
                const uint32_t va = base + AVH + (uint32_t)(kap * 2048) + vrow +
                                    (uint32_t)((((j16 << 1) | vchk) ^ vsw) << 4);
                uint32_t vhf[4], vlf[4];
                ldm_x4_t(vhf, va);
                ldm_x4_t(vlf, va + 16384);
                uint32_t v0h[2] = {vhf[0], vhf[1]}, v1h[2] = {vhf[2], vhf[3]};
                uint32_t v0l[2] = {vlf[0], vlf[1]}, v1l[2] = {vlf[2], vlf[3]};
                mma_bf16(d_y[2*j16],   p_h, v0h);
                mma_bf16(d_y[2*j16],   p_h, v0l);
                mma_bf16(d_y[2*j16],   p_l, v0h);
                mma_bf16(d_y[2*j16+1], p_h, v1h);
                mma_bf16(d_y[2*j16+1], p_h, v1l);
                mma_bf16(d_y[2*j16+1], p_l, v1h);
            }
        }
        __syncthreads();
    }

    // finalize: row sums, write y as bf16 hi/lo
    lsum0 += __shfl_xor_sync(0xffffffffu, lsum0, 1);
    lsum0 += __shfl_xor_sync(0xffffffffu, lsum0, 2);
    lsum1 += __shfl_xor_sync(0xffffffffu, lsum1, 1);
    lsum1 += __shfl_xor_sync(0xffffffffu, lsum1, 2);
    const float inv0 = 1.f / lsum0;
    const float inv1 = 1.f / lsum1;
    if ((lane & 3) == 0) {
        g_lsum[(size_t)bh * Tn + qbase + rl0]     = lsum0;
        g_lsum[(size_t)bh * Tn + qbase + rl0 + 8] = lsum1;
    }
    const int b = bh >> 4, hh = bh & 15;
    const size_t y0i = ((size_t)(b * Tn + qbase + rl0)) * Cn + hh * 64;
    const size_t y1i = y0i + (size_t)8 * Cn;
    #pragma unroll
    for (int j = 0; j < 8; j++) {
        uint32_t h, l;
        split2(d_y[j][0] * inv0, d_y[j][1] * inv0, h, l);
        *(uint32_t*)(g_yh + y0i + 8 * j + cl0) = h;
        *(uint32_t*)(g_yl + y0i + 8 * j + cl0) = l;
        split2(d_y[j][2] * inv1, d_y[j][3] * inv1, h, l);
        *(uint32_t*)(g_yh + y1i + 8 * j + cl0) = h;
        *(uint32_t*)(g_yl + y1i + 8 * j + cl0) = l;
    }
}

// ---------------------------------------------------------------------------
extern "C" void kernel_launch(void* const* d_in, const int* in_sizes, int n_in,
                              void* d_out, int out_size)
{
    const float* x  = (const float*)d_in[0];
    const float* Wq = (const float*)d_in[1];
    const float* bq = (const float*)d_in[2];
    const float* Wk = (const float*)d_in[3];
    const float* bk = (const float*)d_in[4];
    const float* Wv = (const float*)d_in[5];
    const float* bv = (const float*)d_in[6];
    const float* Wp = (const float*)d_in[7];
    const float* bp = (const float*)d_in[8];

    float* y_out   = (float*)d_out;                       // [B,T,C]
    float* att_out = y_out + (size_t)BT * Cn;             // [B,H,T,T]

    cudaFuncSetAttribute(gemm_qkv_tc,  cudaFuncAttributeMaxDynamicSharedMemorySize, GEMM_SMEM);
    cudaFuncSetAttribute(gemm_proj_tc, cudaFuncAttributeMaxDynamicSharedMemorySize, GEMM_SMEM);
    cudaFuncSetAttribute(attn_mma,     cudaFuncAttributeMaxDynamicSharedMemorySize, ATT_SMEM);

    // pre-split x and weights to bf16 hi/lo (one kernel)
    conv_all<<<8192 + 4096, 256>>>((const float4*)x, (const float4*)Wq,
                                   (const float4*)Wk, (const float4*)Wv,
                                   (const float4*)Wp);

    // QKV projections -> bf16 hi/lo q,k,v (q pre-scaled 1/8)
    gemm_qkv_tc<<<dim3(8, 64, 3), 256, GEMM_SMEM>>>(bq, bk, bv);

    // Fused MMA attention: unnormalized E -> att, row sums, y = E@V / l
    attn_mma<<<dim3(NQT, Bn * Hn), 256, ATT_SMEM>>>(att_out);

    // Output projection + att normalization (CTA-specialized, one launch)
    gemm_proj_tc<<<dim3(8, 80), 256, GEMM_SMEM>>>(bp, y_out, att_out);
}

// round 11
// speedup vs baseline: 1.4411x; 1.4411x over previous
#include <cuda_runtime.h>
#include <cuda_bf16.h>
#include <math_constants.h>
#include <cstdint>

#define Bn 4
#define Tn 2048
#define Cn 1024
#define Hn 16
#define Dn 64
#define BT (Bn*Tn)      // 8192
#define NQT (Tn/128)    // 16 q-tiles of 128

typedef unsigned short ushort_t;

// Scratch (device globals — no allocation allowed)
__device__ __align__(16) ushort_t g_qh[(size_t)64*Tn*Dn];   // bf16 hi/lo of q (pre-scaled 0.125)
__device__ __align__(16) ushort_t g_ql[(size_t)64*Tn*Dn];
__device__ __align__(16) ushort_t g_kh[(size_t)64*Tn*Dn];
__device__ __align__(16) ushort_t g_kl[(size_t)64*Tn*Dn];
__device__ __align__(16) ushort_t g_vh[(size_t)64*Tn*Dn];
__device__ __align__(16) ushort_t g_vl[(size_t)64*Tn*Dn];
__device__ __align__(16) ushort_t g_xh[(size_t)BT*Cn];      // x pre-split
__device__ __align__(16) ushort_t g_xl[(size_t)BT*Cn];
__device__ __align__(16) ushort_t g_wh[(size_t)4*Cn*Cn];    // Wq,Wk,Wv,Wp pre-split
__device__ __align__(16) ushort_t g_wl[(size_t)4*Cn*Cn];
__device__ __align__(16) ushort_t g_yh[(size_t)BT*Cn];      // attention out (normalized), pre-split
__device__ __align__(16) ushort_t g_yl[(size_t)BT*Cn];
__device__ float g_lsum[(size_t)64*Tn];                     // softmax row sums (131072 rows)

// ---------------------------------------------------------------------------
// helpers
// ---------------------------------------------------------------------------
__device__ __forceinline__ uint32_t smem_u32(const void* p) {
    uint32_t a;
    asm("{ .reg .u64 t; cvta.to.shared.u64 t, %1; cvt.u32.u64 %0, t; }"
        : "=r"(a) : "l"(p));
    return a;
}

__device__ __forceinline__ void split2(float f0, float f1, uint32_t& hi, uint32_t& lo) {
    __nv_bfloat16 h0 = __float2bfloat16(f0);
    __nv_bfloat16 h1 = __float2bfloat16(f1);
    __nv_bfloat16 l0 = __float2bfloat16(f0 - __bfloat162float(h0));
    __nv_bfloat16 l1 = __float2bfloat16(f1 - __bfloat162float(h1));
    hi = (uint32_t)__bfloat16_as_ushort(h0) | ((uint32_t)__bfloat16_as_ushort(h1) << 16);
    lo = (uint32_t)__bfloat16_as_ushort(l0) | ((uint32_t)__bfloat16_as_ushort(l1) << 16);
}

__device__ __forceinline__ void ldm_x4(uint32_t r[4], uint32_t addr) {
    asm volatile("ldmatrix.sync.aligned.m8n8.x4.shared.b16 {%0,%1,%2,%3}, [%4];"
        : "=r"(r[0]), "=r"(r[1]), "=r"(r[2]), "=r"(r[3]) : "r"(addr));
}

__device__ __forceinline__ void ldm_x4_t(uint32_t r[4], uint32_t addr) {
    asm volatile("ldmatrix.sync.aligned.m8n8.x4.trans.shared.b16 {%0,%1,%2,%3}, [%4];"
        : "=r"(r[0]), "=r"(r[1]), "=r"(r[2]), "=r"(r[3]) : "r"(addr));
}

__device__ __forceinline__ void mma_bf16(float d[4], const uint32_t a[4], const uint32_t b[2]) {
    asm volatile(
        "mma.sync.aligned.m16n8k16.row.col.f32.bf16.bf16.f32 "
        "{%0,%1,%2,%3}, {%4,%5,%6,%7}, {%8,%9}, {%0,%1,%2,%3};"
        : "+f"(d[0]), "+f"(d[1]), "+f"(d[2]), "+f"(d[3])
        : "r"(a[0]), "r"(a[1]), "r"(a[2]), "r"(a[3]), "r"(b[0]), "r"(b[1]));
}

#define CP16(dst, src) asm volatile("cp.async.cg.shared.global [%0], [%1], 16;" :: "r"(dst), "l"(src))
#define CPCOMMIT()     asm volatile("cp.async.commit_group;" ::: "memory")
#define CPWAIT0()      asm volatile("cp.async.wait_group 0;" ::: "memory")
#define CPWAIT1()      asm volatile("cp.async.wait_group 1;" ::: "memory")

// ---------------------------------------------------------------------------
// combined pre-convert kernel: fp32 -> bf16 hi/lo for x and all 4 weights
// ---------------------------------------------------------------------------
__global__ __launch_bounds__(256) void conv_all(
    const float4* __restrict__ x,
    const float4* __restrict__ Wq, const float4* __restrict__ Wk,
    const float4* __restrict__ Wv, const float4* __restrict__ Wp)
{
    int b = blockIdx.x;
    const float4* src;
    uint2 *dh, *dl;
    int i;
    if (b < 8192) {               // x: 2M float4
        i = b * 256 + threadIdx.x;
        src = x; dh = (uint2*)g_xh; dl = (uint2*)g_xl;
    } else {                      // weights: 4 x 256K float4
        b -= 8192;
        const int z = b >> 10;
        src = (z == 0) ? Wq : (z == 1) ? Wk : (z == 2) ? Wv : Wp;
        dh = (uint2*)(g_wh + (size_t)z * Cn * Cn);
        dl = (uint2*)(g_wl + (size_t)z * Cn * Cn);
        i = (b & 1023) * 256 + threadIdx.x;
    }
    float4 v = src[i];
    uint32_t h0, l0, h1, l1;
    split2(v.x, v.y, h0, l0);
    split2(v.z, v.w, h1, l1);
    dh[i] = make_uint2(h0, h1);
    dl[i] = make_uint2(l0, l1);
}

// ===========================================================================
// bf16 pre-split GEMM, cp.async 3-stage, CTA 128x128, warp tile 64x32
// (8 warps: 2m x 4n), ~120 regs -> 2 CTAs/SM.
// Stage: Ah@0 (128x80B), Al@10240, Bh@20480 (32x272B), Bl@29184 => 37888 B.
// ===========================================================================
#define GSTG 37888
#define GEMM_SMEM (3*GSTG)   // 113664

__device__ __forceinline__ void gemm_issue(
    uint32_t sbase,
    const ushort_t* __restrict__ Ah_g, const ushort_t* __restrict__ Al_g,
    const ushort_t* __restrict__ Bh_g, const ushort_t* __restrict__ Bl_g,
    int bm, int bn, int kc, int tid)
{
    #pragma unroll
    for (int i = 0; i < 2; i++) {
        const int ia = tid + 256 * i;
        const int r = ia >> 2, c = ia & 3;
        const uint32_t dst = sbase + (uint32_t)(r * 80 + c * 16);
        const size_t src = (size_t)(bm * 128 + r) * 1024 + kc * 32 + c * 8;
        CP16(dst, Ah_g + src);
        CP16(dst + 10240, Al_g + src);
    }
    #pragma unroll
    for (int i = 0; i < 2; i++) {
        const int ib = tid + 256 * i;
        const int k = ib >> 4, c = ib & 15;
        const uint32_t dst = sbase + (uint32_t)(20480 + k * 272 + c * 16);
        const size_t src = (size_t)(kc * 32 + k) * 1024 + bn * 128 + c * 8;
        CP16(dst, Bh_g + src);
        CP16(dst + 8704, Bl_g + src);
    }
    CPCOMMIT();
}

template<bool REMAP>
__device__ __forceinline__ void gemm2_body(
    const ushort_t* __restrict__ Ah_g, const ushort_t* __restrict__ Al_g,
    const ushort_t* __restrict__ Bh_g, const ushort_t* __restrict__ Bl_g,
    const float* __restrict__ bias, float* __restrict__ out,
    ushort_t* __restrict__ outH, ushort_t* __restrict__ outL, float scl,
    int bm, int bn)
{
    extern __shared__ char smc[];
    const uint32_t sb = smem_u32(smc);
    const int tid = threadIdx.x, wid = tid >> 5, lane = tid & 31;
    const int warp_m = wid & 1;        // 64 rows each
    const int warp_n = wid >> 1;       // 32 cols each

    const int l15 = lane & 15;
    const int lhi = lane >> 4;
    const uint32_t aBase = sb + (uint32_t)((warp_m * 64 + l15) * 80 + lhi * 16);
    const uint32_t bBase = sb + 20480 + (uint32_t)(l15 * 272 + warp_n * 64 + lhi * 16);

    float d[4][4][4];
    #pragma unroll
    for (int t = 0; t < 4; t++)
        #pragma unroll
        for (int u = 0; u < 4; u++)
            #pragma unroll
            for (int v = 0; v < 4; v++) d[t][u][v] = 0.f;

    gemm_issue(sb,        Ah_g, Al_g, Bh_g, Bl_g, bm, bn, 0, tid);
    gemm_issue(sb + GSTG, Ah_g, Al_g, Bh_g, Bl_g, bm, bn, 1, tid);

    for (int kc = 0; kc < 32; kc++) {
        if (kc == 31) { CPWAIT0(); } else { CPWAIT1(); }
        __syncthreads();
        if (kc < 30)
            gemm_issue(sb + (uint32_t)(((kc + 2) % 3) * GSTG),
                       Ah_g, Al_g, Bh_g, Bl_g, bm, bn, kc + 2, tid);

        const uint32_t stgOff = (uint32_t)((kc % 3) * GSTG);

        #pragma unroll
        for (int ss = 0; ss < 2; ss++) {
            uint32_t Bh[4][2], Bl[4][2];
            #pragma unroll
            for (int gp = 0; gp < 2; gp++) {
                const uint32_t ba = bBase + stgOff + (uint32_t)(ss * 16 * 272 + gp * 32);
                uint32_t r[4];
                ldm_x4_t(r, ba);
                Bh[gp*2][0] = r[0]; Bh[gp*2][1] = r[1];
                Bh[gp*2+1][0] = r[2]; Bh[gp*2+1][1] = r[3];
                ldm_x4_t(r, ba + 8704);
                Bl[gp*2][0] = r[0]; Bl[gp*2][1] = r[1];
                Bl[gp*2+1][0] = r[2]; Bl[gp*2+1][1] = r[3];
            }
            #pragma unroll
            for (int t = 0; t < 4; t++) {
                uint32_t Ah[4], Al_[4];
                const uint32_t aa = aBase + stgOff + (uint32_t)(t * 16 * 80 + ss * 32);
                ldm_x4(Ah, aa);
                ldm_x4(Al_, aa + 10240);
                #pragma unroll
                for (int u = 0; u < 4; u++) {
                    mma_bf16(d[t][u], Ah, Bh[u]);
                    mma_bf16(d[t][u], Ah, Bl[u]);
                    mma_bf16(d[t][u], Al_, Bh[u]);
                }
            }
        }
    }

    // ---- epilogue ----
    #pragma unroll
    for (int t = 0; t < 4; t++) {
        const int rowA = bm * 128 + warp_m * 64 + t * 16 + (lane >> 2);
        #pragma unroll
        for (int half = 0; half < 2; half++) {
            const int m = rowA + half * 8;
            #pragma unroll
            for (int u = 0; u < 4; u++) {
                const int col = bn * 128 + warp_n * 32 + u * 8 + ((lane & 3) << 1);
                const float v0 = d[t][u][half * 2 + 0] + __ldg(&bias[col]);
                const float v1 = d[t][u][half * 2 + 1] + __ldg(&bias[col + 1]);
                if (REMAP) {
                    const int b = m >> 11, tt = m & 2047;
                    const int h = col >> 6, d0 = col & 63;
                    const size_t idx = (((size_t)(b * Hn + h) * Tn) + tt) * Dn + d0;
                    uint32_t hh, ll;
                    split2(v0 * scl, v1 * scl, hh, ll);
                    *(uint32_t*)(outH + idx) = hh;
                    *(uint32_t*)(outL + idx) = ll;
                } else {
                    *(float2*)(out + (size_t)m * 1024 + col) = make_float2(v0, v1);
                }
            }
        }
    }
}

__global__ __launch_bounds__(256, 2) void gemm_qkv_tc(
    const float* __restrict__ bq, const float* __restrict__ bk,
    const float* __restrict__ bv)
{
    const float* bias; ushort_t *oh, *ol; float scl;
    if (blockIdx.z == 0)      { bias = bq; oh = g_qh; ol = g_ql; scl = 0.125f; }
    else if (blockIdx.z == 1) { bias = bk; oh = g_kh; ol = g_kl; scl = 1.f; }
    else                      { bias = bv; oh = g_vh; ol = g_vl; scl = 1.f; }
    const size_t wo = (size_t)blockIdx.z * Cn * Cn;
    gemm2_body<true>(g_xh, g_xl, g_wh + wo, g_wl + wo, bias, nullptr, oh, ol, scl,
                     blockIdx.y, blockIdx.x);
}

// ---------------------------------------------------------------------------
// Output projection + att normalization, fine-grained CTA interleave:
//   linear grid of 16896 CTAs; id%33==0 -> GEMM CTA (512 total, proven proj),
//   else -> norm CTA (16384 total, 8 warps x 1 row each = 131072 rows,
//   identical shape to the fast standalone norm kernel).
// ---------------------------------------------------------------------------
__global__ __launch_bounds__(256, 2) void gemm_proj_tc(
    const float* __restrict__ bp, float* __restrict__ out,
    float* __restrict__ att)
{
    const int id = blockIdx.x;
    if (id % 33 != 0) {
        // -------- norm CTA: 8 warps, one row per warp --------
        const int norm_idx = id - id / 33 - 1;             // 0..16383 (bijective)
        const int wid = threadIdx.x >> 5, lane = threadIdx.x & 31;
        const size_t row = (size_t)norm_idx * 8 + wid;     // 0..131071
        const int rs = (int)(row & (Tn - 1));
        const int width = ((rs >> 7) + 1) * 128;
        const float inv = 1.f / g_lsum[row];
        float* p = att + row * Tn;
        for (int c = lane * 4; c < width; c += 128) {
            float4 v = *(float4*)(p + c);
            v.x *= inv; v.y *= inv; v.z *= inv; v.w *= inv;
            *(float4*)(p + c) = v;
        }
        return;
    }
    // -------- GEMM CTA --------
    const int g = id / 33;                                 // 0..511
    const size_t wo = (size_t)3 * Cn * Cn;
    gemm2_body<false>(g_yh, g_yl, g_wh + wo, g_wl + wo, bp, out,
                      nullptr, nullptr, 1.f, g >> 3, g & 7);
}

// ===========================================================================
// MMA attention (R8, unchanged): single pass, unnormalized E -> att,
// y = E@V / l written as bf16 hi/lo.
// ===========================================================================
#define ATT_SMEM 131072
#define AKH 0
#define AKL 16384
#define AVH 32768
#define AVL 49152

__global__ __launch_bounds__(256, 1) void attn_mma(float* __restrict__ att)
{
    extern __shared__ char smc[];
    const uint32_t sb = smem_u32(smc);
    const int tid = threadIdx.x, wid = tid >> 5, lane = tid & 31;
    const int bh = blockIdx.y;
    const int qt = (NQT - 1) - blockIdx.x;
    const int qbase = qt * 128;
    const int nkt = qt + 1;

    const ushort_t* qh = g_qh + ((size_t)bh * Tn + qbase) * Dn;
    const ushort_t* ql = g_ql + ((size_t)bh * Tn + qbase) * Dn;
    const ushort_t* khp = g_kh + (size_t)bh * Tn * Dn;
    const ushort_t* klp = g_kl + (size_t)bh * Tn * Dn;
    const ushort_t* vhp = g_vh + (size_t)bh * Tn * Dn;
    const ushort_t* vlp = g_vl + (size_t)bh * Tn * Dn;
    float* attp = att + ((size_t)bh * Tn + qbase) * Tn;

    // Q stage into buffer0
    #pragma unroll
    for (int i = 0; i < 4; i++) {
        const int idx = tid + 256 * i;
        const int r = idx >> 3, c = idx & 7;
        const uint32_t off = (uint32_t)(r * 128 + ((c ^ (r & 7)) << 4));
        CP16(sb + AKH + off, qh + r * 64 + c * 8);
        CP16(sb + AKL + off, ql + r * 64 + c * 8);
    }
    CPCOMMIT();

    // K/V tile 0 into buffer1
    {
        const uint32_t base = sb + 65536;
        #pragma unroll
        for (int i = 0; i < 4; i++) {
            const int idx = tid + 256 * i;
            const int r = idx >> 3, c = idx & 7;
            const uint32_t off = (uint32_t)(r * 128 + ((c ^ (r & 7)) << 4));
            const size_t so = (size_t)r * 64 + c * 8;
            CP16(base + AKH + off, khp + so);
            CP16(base + AKL + off, klp + so);
            CP16(base + AVH + off, vhp + so);
            CP16(base + AVL + off, vlp + so);
        }
        CPCOMMIT();
    }

    // zero-fill strict-upper tiles while the async loads fly
    const int zstart = nkt * 128;
    #pragma unroll 1
    for (int rg = 0; rg < 16; rg++) {
        const int r = rg * 8 + wid;
        for (int c = zstart + lane * 4; c < Tn; c += 128)
            *(float4*)(attp + (size_t)r * Tn + c) = make_float4(0.f, 0.f, 0.f, 0.f);
    }

    CPWAIT1();
    __syncthreads();

    uint32_t q_h[4][4], q_l[4][4];
    {
        const int arow = 16 * wid + ((lane >> 3) & 1) * 8 + (lane & 7);
        #pragma unroll
        for (int kk = 0; kk < 4; kk++) {
            const uint32_t addr = sb + AKH + (uint32_t)(arow * 128 +
                (((2 * kk + (lane >> 4)) ^ (arow & 7)) << 4));
            ldm_x4(q_h[kk], addr);
            ldm_x4(q_l[kk], addr + 16384);
        }
    }
    __syncthreads();

    const int bkeyL = ((lane >> 4) << 3) + (lane & 7);
    const int bchk  = (lane >> 3) & 1;
    const uint32_t brow = (uint32_t)(bkeyL * 128);
    const int bsw = bkeyL & 7;

    const int vkeyL = ((lane >> 3) & 1) * 8 + (lane & 7);
    const int vchk  = lane >> 4;
    const uint32_t vrow = (uint32_t)(vkeyL * 128);
    const int vsw = vkeyL & 7;

    const int rl0 = 16 * wid + (lane >> 2);
    const int cl0 = 2 * (lane & 3);

    float d_y[8][4];
    #pragma unroll
    for (int j = 0; j < 8; j++)
        #pragma unroll
        for (int v = 0; v < 4; v++) d_y[j][v] = 0.f;
    float lsum0 = 0.f, lsum1 = 0.f;

    for (int kt = 0; kt < nkt; kt++) {
        const int buf = (kt + 1) & 1;
        if (kt + 1 < nkt) {
            const uint32_t base = sb + (uint32_t)((kt & 1) * 65536);
            const size_t tof = (size_t)(kt + 1) * 128 * 64;
            #pragma unroll
            for (int i = 0; i < 4; i++) {
                const int idx = tid + 256 * i;
                const int r = idx >> 3, c = idx & 7;
                const uint32_t off = (uint32_t)(r * 128 + ((c ^ (r & 7)) << 4));
                const size_t so = tof + (size_t)r * 64 + c * 8;
                CP16(base + AKH + off, khp + so);
                CP16(base + AKL + off, klp + so);
                CP16(base + AVH + off, vhp + so);
                CP16(base + AVL + off, vlp + so);
            }
            CPCOMMIT();
            CPWAIT1();
        } else {
            CPWAIT0();
        }
        __syncthreads();

        const uint32_t base = sb + (uint32_t)(buf * 65536);

        float ds[16][4];
        #pragma unroll
        for (int j = 0; j < 16; j++)
            #pragma unroll
            for (int v = 0; v < 4; v++) ds[j][v] = 0.f;

        #pragma unroll
        for (int kk = 0; kk < 4; kk++) {
            #pragma unroll
            for (int j16 = 0; j16 < 8; j16++) {
                const uint32_t ka = base + AKH + (uint32_t)(j16 * 2048) + brow +
                                    (uint32_t)((((kk << 1) | bchk) ^ bsw) << 4);
                uint32_t khf[4], klf[4];
                ldm_x4(khf, ka);
                ldm_x4(klf, ka + 16384);
                uint32_t b0h[2] = {khf[0], khf[1]}, b1h[2] = {khf[2], khf[3]};
                uint32_t b0l[2] = {klf[0], klf[1]}, b1l[2] = {klf[2], klf[3]};
                mma_bf16(ds[2*j16],   q_h[kk], b0h);
                mma_bf16(ds[2*j16],   q_h[kk], b0l);
                mma_bf16(ds[2*j16],   q_l[kk], b0h);
                mma_bf16(ds[2*j16+1], q_h[kk], b1h);
                mma_bf16(ds[2*j16+1], q_h[kk], b1l);
                mma_bf16(ds[2*j16+1], q_l[kk], b1h);
            }
        }

        const bool diag = (kt == qt);
        const int ktbase = kt * 128;
        #pragma unroll
        for (int j = 0; j < 16; j++) {
            const int c = 8 * j + cl0;
            float e00 = __expf(ds[j][0]);
            float e01 = __expf(ds[j][1]);
            float e10 = __expf(ds[j][2]);
            float e11 = __expf(ds[j][3]);
            if (diag) {
                if (c     > rl0)     e00 = 0.f;
                if (c + 1 > rl0)     e01 = 0.f;
                if (c     > rl0 + 8) e10 = 0.f;
                if (c + 1 > rl0 + 8) e11 = 0.f;
            }
            ds[j][0] = e00; ds[j][1] = e01; ds[j][2] = e10; ds[j][3] = e11;
            *(float2*)(attp + (size_t)rl0 * Tn + ktbase + c)       = make_float2(e00, e01);
            *(float2*)(attp + (size_t)(rl0 + 8) * Tn + ktbase + c) = make_float2(e10, e11);
            lsum0 += e00 + e01;
            lsum1 += e10 + e11;
        }

        #pragma unroll
        for (int kap = 0; kap < 8; kap++) {
            uint32_t p_h[4], p_l[4];
            split2(ds[2*kap][0],   ds[2*kap][1],   p_h[0], p_l[0]);
            split2(ds[2*kap][2],   ds[2*kap][3],   p_h[1], p_l[1]);
            split2(ds[2*kap+1][0], ds[2*kap+1][1], p_h[2], p_l[2]);
            split2(ds[2*kap+1][2], ds[2*kap+1][3], p_h[3], p_l[3]);
            #pragma unroll
            for (int j16 = 0; j16 < 4; j16++) {
                const uint32_t va = base + AVH + (uint32_t)(kap * 2048) + vrow +
                                    (uint32_t)((((j16 << 1) | vchk) ^ vsw) << 4);
                uint32_t vhf[4], vlf[4];
                ldm_x4_t(vhf, va);
                ldm_x4_t(vlf, va + 16384);
                uint32_t v0h[2] = {vhf[0], vhf[1]}, v1h[2] = {vhf[2], vhf[3]};
                uint32_t v0l[2] = {vlf[0], vlf[1]}, v1l[2] = {vlf[2], vlf[3]};
                mma_bf16(d_y[2*j16],   p_h, v0h);
                mma_bf16(d_y[2*j16],   p_h, v0l);
                mma_bf16(d_y[2*j16],   p_l, v0h);
                mma_bf16(d_y[2*j16+1], p_h, v1h);
                mma_bf16(d_y[2*j16+1], p_h, v1l);
                mma_bf16(d_y[2*j16+1], p_l, v1h);
            }
        }
        __syncthreads();
    }

    // finalize: row sums, write y as bf16 hi/lo
    lsum0 += __shfl_xor_sync(0xffffffffu, lsum0, 1);
    lsum0 += __shfl_xor_sync(0xffffffffu, lsum0, 2);
    lsum1 += __shfl_xor_sync(0xffffffffu, lsum1, 1);
    lsum1 += __shfl_xor_sync(0xffffffffu, lsum1, 2);
    const float inv0 = 1.f / lsum0;
    const float inv1 = 1.f / lsum1;
    if ((lane & 3) == 0) {
        g_lsum[(size_t)bh * Tn + qbase + rl0]     = lsum0;
        g_lsum[(size_t)bh * Tn + qbase + rl0 + 8] = lsum1;
    }
    const int b = bh >> 4, hh = bh & 15;
    const size_t y0i = ((size_t)(b * Tn + qbase + rl0)) * Cn + hh * 64;
    const size_t y1i = y0i + (size_t)8 * Cn;
    #pragma unroll
    for (int j = 0; j < 8; j++) {
        uint32_t h, l;
        split2(d_y[j][0] * inv0, d_y[j][1] * inv0, h, l);
        *(uint32_t*)(g_yh + y0i + 8 * j + cl0) = h;
        *(uint32_t*)(g_yl + y0i + 8 * j + cl0) = l;
        split2(d_y[j][2] * inv1, d_y[j][3] * inv1, h, l);
        *(uint32_t*)(g_yh + y1i + 8 * j + cl0) = h;
        *(uint32_t*)(g_yl + y1i + 8 * j + cl0) = l;
    }
}

// ---------------------------------------------------------------------------
extern "C" void kernel_launch(void* const* d_in, const int* in_sizes, int n_in,
                              void* d_out, int out_size)
{
    const float* x  = (const float*)d_in[0];
    const float* Wq = (const float*)d_in[1];
    const float* bq = (const float*)d_in[2];
    const float* Wk = (const float*)d_in[3];
    const float* bk = (const float*)d_in[4];
    const float* Wv = (const float*)d_in[5];
    const float* bv = (const float*)d_in[6];
    const float* Wp = (const float*)d_in[7];
    const float* bp = (const float*)d_in[8];

    float* y_out   = (float*)d_out;                       // [B,T,C]
    float* att_out = y_out + (size_t)BT * Cn;             // [B,H,T,T]

    cudaFuncSetAttribute(gemm_qkv_tc,  cudaFuncAttributeMaxDynamicSharedMemorySize, GEMM_SMEM);
    cudaFuncSetAttribute(gemm_proj_tc, cudaFuncAttributeMaxDynamicSharedMemorySize, GEMM_SMEM);
    cudaFuncSetAttribute(attn_mma,     cudaFuncAttributeMaxDynamicSharedMemorySize, ATT_SMEM);

    // pre-split x and weights to bf16 hi/lo (one kernel)
    conv_all<<<8192 + 4096, 256>>>((const float4*)x, (const float4*)Wq,
                                   (const float4*)Wk, (const float4*)Wv,
                                   (const float4*)Wp);

    // QKV projections -> bf16 hi/lo q,k,v (q pre-scaled 1/8)
    gemm_qkv_tc<<<dim3(8, 64, 3), 256, GEMM_SMEM>>>(bq, bk, bv);

    // Fused MMA attention: unnormalized E -> att, row sums, y = E@V / l
    attn_mma<<<dim3(NQT, Bn * Hn), 256, ATT_SMEM>>>(att_out);

    // Output projection + att normalization (interleaved CTA mix, one launch)
    gemm_proj_tc<<<16896, 256, GEMM_SMEM>>>(bp, y_out, att_out);
}

// round 12
// speedup vs baseline: 1.4561x; 1.0105x over previous
#include <cuda_runtime.h>
#include <cuda_bf16.h>
#include <math_constants.h>
#include <cstdint>

#define Bn 4
#define Tn 2048
#define Cn 1024
#define Hn 16
#define Dn 64
#define BT (Bn*Tn)      // 8192
#define NQT (Tn/128)    // 16 q-tiles of 128

typedef unsigned short ushort_t;

// Scratch (device globals — no allocation allowed)
__device__ __align__(16) ushort_t g_qh[(size_t)64*Tn*Dn];   // bf16 hi/lo of q (pre-scaled 0.125)
__device__ __align__(16) ushort_t g_ql[(size_t)64*Tn*Dn];
__device__ __align__(16) ushort_t g_kh[(size_t)64*Tn*Dn];
__device__ __align__(16) ushort_t g_kl[(size_t)64*Tn*Dn];
__device__ __align__(16) ushort_t g_vh[(size_t)64*Tn*Dn];
__device__ __align__(16) ushort_t g_vl[(size_t)64*Tn*Dn];
__device__ __align__(16) ushort_t g_xh[(size_t)BT*Cn];      // x pre-split
__device__ __align__(16) ushort_t g_xl[(size_t)BT*Cn];
__device__ __align__(16) ushort_t g_wh[(size_t)4*Cn*Cn];    // Wq,Wk,Wv,Wp pre-split
__device__ __align__(16) ushort_t g_wl[(size_t)4*Cn*Cn];
__device__ __align__(16) ushort_t g_yh[(size_t)BT*Cn];      // attention out (normalized), pre-split
__device__ __align__(16) ushort_t g_yl[(size_t)BT*Cn];

// ---------------------------------------------------------------------------
// helpers
// ---------------------------------------------------------------------------
__device__ __forceinline__ uint32_t smem_u32(const void* p) {
    uint32_t a;
    asm("{ .reg .u64 t; cvta.to.shared.u64 t, %1; cvt.u32.u64 %0, t; }"
        : "=r"(a) : "l"(p));
    return a;
}

__device__ __forceinline__ void split2(float f0, float f1, uint32_t& hi, uint32_t& lo) {
    __nv_bfloat16 h0 = __float2bfloat16(f0);
    __nv_bfloat16 h1 = __float2bfloat16(f1);
    __nv_bfloat16 l0 = __float2bfloat16(f0 - __bfloat162float(h0));
    __nv_bfloat16 l1 = __float2bfloat16(f1 - __bfloat162float(h1));
    hi = (uint32_t)__bfloat16_as_ushort(h0) | ((uint32_t)__bfloat16_as_ushort(h1) << 16);
    lo = (uint32_t)__bfloat16_as_ushort(l0) | ((uint32_t)__bfloat16_as_ushort(l1) << 16);
}

__device__ __forceinline__ void ldm_x4(uint32_t r[4], uint32_t addr) {
    asm volatile("ldmatrix.sync.aligned.m8n8.x4.shared.b16 {%0,%1,%2,%3}, [%4];"
        : "=r"(r[0]), "=r"(r[1]), "=r"(r[2]), "=r"(r[3]) : "r"(addr));
}

__device__ __forceinline__ void ldm_x4_t(uint32_t r[4], uint32_t addr) {
    asm volatile("ldmatrix.sync.aligned.m8n8.x4.trans.shared.b16 {%0,%1,%2,%3}, [%4];"
        : "=r"(r[0]), "=r"(r[1]), "=r"(r[2]), "=r"(r[3]) : "r"(addr));
}

__device__ __forceinline__ void mma_bf16(float d[4], const uint32_t a[4], const uint32_t b[2]) {
    asm volatile(
        "mma.sync.aligned.m16n8k16.row.col.f32.bf16.bf16.f32 "
        "{%0,%1,%2,%3}, {%4,%5,%6,%7}, {%8,%9}, {%0,%1,%2,%3};"
        : "+f"(d[0]), "+f"(d[1]), "+f"(d[2]), "+f"(d[3])
        : "r"(a[0]), "r"(a[1]), "r"(a[2]), "r"(a[3]), "r"(b[0]), "r"(b[1]));
}

#define CP16(dst, src) asm volatile("cp.async.cg.shared.global [%0], [%1], 16;" :: "r"(dst), "l"(src))
#define CPCOMMIT()     asm volatile("cp.async.commit_group;" ::: "memory")
#define CPWAIT0()      asm volatile("cp.async.wait_group 0;" ::: "memory")
#define CPWAIT1()      asm volatile("cp.async.wait_group 1;" ::: "memory")

// ---------------------------------------------------------------------------
// combined pre-convert kernel: fp32 -> bf16 hi/lo for x and all 4 weights
// ---------------------------------------------------------------------------
__global__ __launch_bounds__(256) void conv_all(
    const float4* __restrict__ x,
    const float4* __restrict__ Wq, const float4* __restrict__ Wk,
    const float4* __restrict__ Wv, const float4* __restrict__ Wp)
{
    int b = blockIdx.x;
    const float4* src;
    uint2 *dh, *dl;
    int i;
    if (b < 8192) {               // x: 2M float4
        i = b * 256 + threadIdx.x;
        src = x; dh = (uint2*)g_xh; dl = (uint2*)g_xl;
    } else {                      // weights: 4 x 256K float4
        b -= 8192;
        const int z = b >> 10;
        src = (z == 0) ? Wq : (z == 1) ? Wk : (z == 2) ? Wv : Wp;
        dh = (uint2*)(g_wh + (size_t)z * Cn * Cn);
        dl = (uint2*)(g_wl + (size_t)z * Cn * Cn);
        i = (b & 1023) * 256 + threadIdx.x;
    }
    float4 v = src[i];
    uint32_t h0, l0, h1, l1;
    split2(v.x, v.y, h0, l0);
    split2(v.z, v.w, h1, l1);
    dh[i] = make_uint2(h0, h1);
    dl[i] = make_uint2(l0, l1);
}

// ===========================================================================
// bf16 pre-split GEMM, cp.async 3-stage, CTA 128x128, warp tile 64x32
// (8 warps: 2m x 4n), ~120 regs -> 2 CTAs/SM.
// Stage: Ah@0 (128x80B), Al@10240, Bh@20480 (32x272B), Bl@29184 => 37888 B.
// ===========================================================================
#define GSTG 37888
#define GEMM_SMEM (3*GSTG)   // 113664

__device__ __forceinline__ void gemm_issue(
    uint32_t sbase,
    const ushort_t* __restrict__ Ah_g, const ushort_t* __restrict__ Al_g,
    const ushort_t* __restrict__ Bh_g, const ushort_t* __restrict__ Bl_g,
    int bm, int bn, int kc, int tid)
{
    #pragma unroll
    for (int i = 0; i < 2; i++) {
        const int ia = tid + 256 * i;
        const int r = ia >> 2, c = ia & 3;
        const uint32_t dst = sbase + (uint32_t)(r * 80 + c * 16);
        const size_t src = (size_t)(bm * 128 + r) * 1024 + kc * 32 + c * 8;
        CP16(dst, Ah_g + src);
        CP16(dst + 10240, Al_g + src);
    }
    #pragma unroll
    for (int i = 0; i < 2; i++) {
        const int ib = tid + 256 * i;
        const int k = ib >> 4, c = ib & 15;
        const uint32_t dst = sbase + (uint32_t)(20480 + k * 272 + c * 16);
        const size_t src = (size_t)(kc * 32 + k) * 1024 + bn * 128 + c * 8;
        CP16(dst, Bh_g + src);
        CP16(dst + 8704, Bl_g + src);
    }
    CPCOMMIT();
}

template<bool REMAP>
__device__ __forceinline__ void gemm2_body(
    const ushort_t* __restrict__ Ah_g, const ushort_t* __restrict__ Al_g,
    const ushort_t* __restrict__ Bh_g, const ushort_t* __restrict__ Bl_g,
    const float* __restrict__ bias, float* __restrict__ out,
    ushort_t* __restrict__ outH, ushort_t* __restrict__ outL, float scl)
{
    extern __shared__ char smc[];
    const uint32_t sb = smem_u32(smc);
    const int tid = threadIdx.x, wid = tid >> 5, lane = tid & 31;
    const int bm = blockIdx.y, bn = blockIdx.x;
    const int warp_m = wid & 1;        // 64 rows each
    const int warp_n = wid >> 1;       // 32 cols each

    const int l15 = lane & 15;
    const int lhi = lane >> 4;
    const uint32_t aBase = sb + (uint32_t)((warp_m * 64 + l15) * 80 + lhi * 16);
    const uint32_t bBase = sb + 20480 + (uint32_t)(l15 * 272 + warp_n * 64 + lhi * 16);

    float d[4][4][4];
    #pragma unroll
    for (int t = 0; t < 4; t++)
        #pragma unroll
        for (int u = 0; u < 4; u++)
            #pragma unroll
            for (int v = 0; v < 4; v++) d[t][u][v] = 0.f;

    gemm_issue(sb,        Ah_g, Al_g, Bh_g, Bl_g, bm, bn, 0, tid);
    gemm_issue(sb + GSTG, Ah_g, Al_g, Bh_g, Bl_g, bm, bn, 1, tid);

    for (int kc = 0; kc < 32; kc++) {
        if (kc == 31) { CPWAIT0(); } else { CPWAIT1(); }
        __syncthreads();
        if (kc < 30)
            gemm_issue(sb + (uint32_t)(((kc + 2) % 3) * GSTG),
                       Ah_g, Al_g, Bh_g, Bl_g, bm, bn, kc + 2, tid);

        const uint32_t stgOff = (uint32_t)((kc % 3) * GSTG);

        #pragma unroll
        for (int ss = 0; ss < 2; ss++) {
            uint32_t Bh[4][2], Bl[4][2];
            #pragma unroll
            for (int gp = 0; gp < 2; gp++) {
                const uint32_t ba = bBase + stgOff + (uint32_t)(ss * 16 * 272 + gp * 32);
                uint32_t r[4];
                ldm_x4_t(r, ba);
                Bh[gp*2][0] = r[0]; Bh[gp*2][1] = r[1];
                Bh[gp*2+1][0] = r[2]; Bh[gp*2+1][1] = r[3];
                ldm_x4_t(r, ba + 8704);
                Bl[gp*2][0] = r[0]; Bl[gp*2][1] = r[1];
                Bl[gp*2+1][0] = r[2]; Bl[gp*2+1][1] = r[3];
            }
            #pragma unroll
            for (int t = 0; t < 4; t++) {
                uint32_t Ah[4], Al_[4];
                const uint32_t aa = aBase + stgOff + (uint32_t)(t * 16 * 80 + ss * 32);
                ldm_x4(Ah, aa);
                ldm_x4(Al_, aa + 10240);
                #pragma unroll
                for (int u = 0; u < 4; u++) {
                    mma_bf16(d[t][u], Ah, Bh[u]);
                    mma_bf16(d[t][u], Ah, Bl[u]);
                    mma_bf16(d[t][u], Al_, Bh[u]);
                }
            }
        }
    }

    // ---- epilogue ----
    #pragma unroll
    for (int t = 0; t < 4; t++) {
        const int rowA = bm * 128 + warp_m * 64 + t * 16 + (lane >> 2);
        #pragma unroll
        for (int half = 0; half < 2; half++) {
            const int m = rowA + half * 8;
            #pragma unroll
            for (int u = 0; u < 4; u++) {
                const int col = bn * 128 + warp_n * 32 + u * 8 + ((lane & 3) << 1);
                const float v0 = d[t][u][half * 2 + 0] + __ldg(&bias[col]);
                const float v1 = d[t][u][half * 2 + 1] + __ldg(&bias[col + 1]);
                if (REMAP) {
                    const int b = m >> 11, tt = m & 2047;
                    const int h = col >> 6, d0 = col & 63;
                    const size_t idx = (((size_t)(b * Hn + h) * Tn) + tt) * Dn + d0;
                    uint32_t hh, ll;
                    split2(v0 * scl, v1 * scl, hh, ll);
                    *(uint32_t*)(outH + idx) = hh;
                    *(uint32_t*)(outL + idx) = ll;
                } else {
                    *(float2*)(out + (size_t)m * 1024 + col) = make_float2(v0, v1);
                }
            }
        }
    }
}

__global__ __launch_bounds__(256, 2) void gemm_qkv_tc(
    const float* __restrict__ bq, const float* __restrict__ bk,
    const float* __restrict__ bv)
{
    const float* bias; ushort_t *oh, *ol; float scl;
    if (blockIdx.z == 0)      { bias = bq; oh = g_qh; ol = g_ql; scl = 0.125f; }
    else if (blockIdx.z == 1) { bias = bk; oh = g_kh; ol = g_kl; scl = 1.f; }
    else                      { bias = bv; oh = g_vh; ol = g_vl; scl = 1.f; }
    const size_t wo = (size_t)blockIdx.z * Cn * Cn;
    gemm2_body<true>(g_xh, g_xl, g_wh + wo, g_wl + wo, bias, nullptr, oh, ol, scl);
}

__global__ __launch_bounds__(256, 2) void gemm_proj_tc(
    const float* __restrict__ bp, float* __restrict__ out)
{
    const size_t wo = (size_t)3 * Cn * Cn;
    gemm2_body<false>(g_yh, g_yl, g_wh + wo, g_wl + wo, bp, out, nullptr, nullptr, 1.f);
}

// ===========================================================================
// MMA attention: single pass, unnormalized E -> att, y = E@V / l (bf16 out),
// then IN-PLACE normalization of this CTA's own att rows (L2-resident).
// ===========================================================================
#define ATT_SMEM 131072
#define AKH 0
#define AKL 16384
#define AVH 32768
#define AVL 49152

__global__ __launch_bounds__(256, 1) void attn_mma(float* __restrict__ att)
{
    extern __shared__ char smc[];
    const uint32_t sb = smem_u32(smc);
    const int tid = threadIdx.x, wid = tid >> 5, lane = tid & 31;
    const int bh = blockIdx.y;
    const int qt = (NQT - 1) - blockIdx.x;
    const int qbase = qt * 128;
    const int nkt = qt + 1;

    const ushort_t* qh = g_qh + ((size_t)bh * Tn + qbase) * Dn;
    const ushort_t* ql = g_ql + ((size_t)bh * Tn + qbase) * Dn;
    const ushort_t* khp = g_kh + (size_t)bh * Tn * Dn;
    const ushort_t* klp = g_kl + (size_t)bh * Tn * Dn;
    const ushort_t* vhp = g_vh + (size_t)bh * Tn * Dn;
    const ushort_t* vlp = g_vl + (size_t)bh * Tn * Dn;
    float* attp = att + ((size_t)bh * Tn + qbase) * Tn;

    // Q stage into buffer0
    #pragma unroll
    for (int i = 0; i < 4; i++) {
        const int idx = tid + 256 * i;
        const int r = idx >> 3, c = idx & 7;
        const uint32_t off = (uint32_t)(r * 128 + ((c ^ (r & 7)) << 4));
        CP16(sb + AKH + off, qh + r * 64 + c * 8);
        CP16(sb + AKL + off, ql + r * 64 + c * 8);
    }
    CPCOMMIT();

    // K/V tile 0 into buffer1
    {
        const uint32_t base = sb + 65536;
        #pragma unroll
        for (int i = 0; i < 4; i++) {
            const int idx = tid + 256 * i;
            const int r = idx >> 3, c = idx & 7;
            const uint32_t off = (uint32_t)(r * 128 + ((c ^ (r & 7)) << 4));
            const size_t so = (size_t)r * 64 + c * 8;
            CP16(base + AKH + off, khp + so);
            CP16(base + AKL + off, klp + so);
            CP16(base + AVH + off, vhp + so);
            CP16(base + AVL + off, vlp + so);
        }
        CPCOMMIT();
    }

    // zero-fill strict-upper tiles while the async loads fly
    const int zstart = nkt * 128;
    #pragma unroll 1
    for (int rg = 0; rg < 16; rg++) {
        const int r = rg * 8 + wid;
        for (int c = zstart + lane * 4; c < Tn; c += 128)
            *(float4*)(attp + (size_t)r * Tn + c) = make_float4(0.f, 0.f, 0.f, 0.f);
    }

    CPWAIT1();
    __syncthreads();

    uint32_t q_h[4][4], q_l[4][4];
    {
        const int arow = 16 * wid + ((lane >> 3) & 1) * 8 + (lane & 7);
        #pragma unroll
        for (int kk = 0; kk < 4; kk++) {
            const uint32_t addr = sb + AKH + (uint32_t)(arow * 128 +
                (((2 * kk + (lane >> 4)) ^ (arow & 7)) << 4));
            ldm_x4(q_h[kk], addr);
            ldm_x4(q_l[kk], addr + 16384);
        }
    }
    __syncthreads();

    const int bkeyL = ((lane >> 4) << 3) + (lane & 7);
    const int bchk  = (lane >> 3) & 1;
    const uint32_t brow = (uint32_t)(bkeyL * 128);
    const int bsw = bkeyL & 7;

    const int vkeyL = ((lane >> 3) & 1) * 8 + (lane & 7);
    const int vchk  = lane >> 4;
    const uint32_t vrow = (uint32_t)(vkeyL * 128);
    const int vsw = vkeyL & 7;

    const int rl0 = 16 * wid + (lane >> 2);
    const int cl0 = 2 * (lane & 3);

    float d_y[8][4];
    #pragma unroll
    for (int j = 0; j < 8; j++)
        #pragma unroll
        for (int v = 0; v < 4; v++) d_y[j][v] = 0.f;
    float lsum0 = 0.f, lsum1 = 0.f;

    for (int kt = 0; kt < nkt; kt++) {
        const int buf = (kt + 1) & 1;
        if (kt + 1 < nkt) {
            const uint32_t base = sb + (uint32_t)((kt & 1) * 65536);
            const size_t tof = (size_t)(kt + 1) * 128 * 64;
            #pragma unroll
            for (int i = 0; i < 4; i++) {
                const int idx = tid + 256 * i;
                const int r = idx >> 3, c = idx & 7;
                const uint32_t off = (uint32_t)(r * 128 + ((c ^ (r & 7)) << 4));
                const size_t so = tof + (size_t)r * 64 + c * 8;
                CP16(base + AKH + off, khp + so);
                CP16(base + AKL + off, klp + so);
                CP16(base + AVH + off, vhp + so);
                CP16(base + AVL + off, vlp + so);
            }
            CPCOMMIT();
            CPWAIT1();
        } else {
            CPWAIT0();
        }
        __syncthreads();

        const uint32_t base = sb + (uint32_t)(buf * 65536);

        float ds[16][4];
        #pragma unroll
        for (int j = 0; j < 16; j++)
            #pragma unroll
            for (int v = 0; v < 4; v++) ds[j][v] = 0.f;

        #pragma unroll
        for (int kk = 0; kk < 4; kk++) {
            #pragma unroll
            for (int j16 = 0; j16 < 8; j16++) {
                const uint32_t ka = base + AKH + (uint32_t)(j16 * 2048) + brow +
                                    (uint32_t)((((kk << 1) | bchk) ^ bsw) << 4);
                uint32_t khf[4], klf[4];
                ldm_x4(khf, ka);
                ldm_x4(klf, ka + 16384);
                uint32_t b0h[2] = {khf[0], khf[1]}, b1h[2] = {khf[2], khf[3]};
                uint32_t b0l[2] = {klf[0], klf[1]}, b1l[2] = {klf[2], klf[3]};
                mma_bf16(ds[2*j16],   q_h[kk], b0h);
                mma_bf16(ds[2*j16],   q_h[kk], b0l);
                mma_bf16(ds[2*j16],   q_l[kk], b0h);
                mma_bf16(ds[2*j16+1], q_h[kk], b1h);
                mma_bf16(ds[2*j16+1], q_h[kk], b1l);
                mma_bf16(ds[2*j16+1], q_l[kk], b1h);
            }
        }

        const bool diag = (kt == qt);
        const int ktbase = kt * 128;
        #pragma unroll
        for (int j = 0; j < 16; j++) {
            const int c = 8 * j + cl0;
            float e00 = __expf(ds[j][0]);
            float e01 = __expf(ds[j][1]);
            float e10 = __expf(ds[j][2]);
            float e11 = __expf(ds[j][3]);
            if (diag) {
                if (c     > rl0)     e00 = 0.f;
                if (c + 1 > rl0)     e01 = 0.f;
                if (c     > rl0 + 8) e10 = 0.f;
                if (c + 1 > rl0 + 8) e11 = 0.f;
            }
            ds[j][0] = e00; ds[j][1] = e01; ds[j][2] = e10; ds[j][3] = e11;
            *(float2*)(attp + (size_t)rl0 * Tn + ktbase + c)       = make_float2(e00, e01);
            *(float2*)(attp + (size_t)(rl0 + 8) * Tn + ktbase + c) = make_float2(e10, e11);
            lsum0 += e00 + e01;
            lsum1 += e10 + e11;
        }

        #pragma unroll
        for (int kap = 0; kap < 8; kap++) {
            uint32_t p_h[4], p_l[4];
            split2(ds[2*kap][0],   ds[2*kap][1],   p_h[0], p_l[0]);
            split2(ds[2*kap][2],   ds[2*kap][3],   p_h[1], p_l[1]);
            split2(ds[2*kap+1][0], ds[2*kap+1][1], p_h[2], p_l[2]);
            split2(ds[2*kap+1][2], ds[2*kap+1][3], p_h[3], p_l[3]);
            #pragma unroll
            for (int j16 = 0; j16 < 4; j16++) {
                const uint32_t va = base + AVH + (uint32_t)(kap * 2048) + vrow +
                                    (uint32_t)((((j16 << 1) | vchk) ^ vsw) << 4);
                uint32_t vhf[4], vlf[4];
                ldm_x4_t(vhf, va);
                ldm_x4_t(vlf, va + 16384);
                uint32_t v0h[2] = {vhf[0], vhf[1]}, v1h[2] = {vhf[2], vhf[3]};
                uint32_t v0l[2] = {vlf[0], vlf[1]}, v1l[2] = {vlf[2], vlf[3]};
                mma_bf16(d_y[2*j16],   p_h, v0h);
                mma_bf16(d_y[2*j16],   p_h, v0l);
                mma_bf16(d_y[2*j16],   p_l, v0h);
                mma_bf16(d_y[2*j16+1], p_h, v1h);
                mma_bf16(d_y[2*j16+1], p_h, v1l);
                mma_bf16(d_y[2*j16+1], p_l, v1h);
            }
        }
        __syncthreads();
    }

    // ---- finalize row sums ----
    lsum0 += __shfl_xor_sync(0xffffffffu, lsum0, 1);
    lsum0 += __shfl_xor_sync(0xffffffffu, lsum0, 2);
    lsum1 += __shfl_xor_sync(0xffffffffu, lsum1, 1);
    lsum1 += __shfl_xor_sync(0xffffffffu, lsum1, 2);
    const float inv0 = 1.f / lsum0;
    const float inv1 = 1.f / lsum1;

    // stash 1/l per row in (now-dead) SMEM buffers
    float* smf = (float*)smc;
    if ((lane & 3) == 0) {
        smf[rl0]     = inv0;
        smf[rl0 + 8] = inv1;
    }

    // ---- write y as bf16 hi/lo ----
    const int b = bh >> 4, hh = bh & 15;
    const size_t y0i = ((size_t)(b * Tn + qbase + rl0)) * Cn + hh * 64;
    const size_t y1i = y0i + (size_t)8 * Cn;
    #pragma unroll
    for (int j = 0; j < 8; j++) {
        uint32_t h, l;
        split2(d_y[j][0] * inv0, d_y[j][1] * inv0, h, l);
        *(uint32_t*)(g_yh + y0i + 8 * j + cl0) = h;
        *(uint32_t*)(g_yl + y0i + 8 * j + cl0) = l;
        split2(d_y[j][2] * inv1, d_y[j][3] * inv1, h, l);
        *(uint32_t*)(g_yh + y1i + 8 * j + cl0) = h;
        *(uint32_t*)(g_yl + y1i + 8 * j + cl0) = l;
    }

    // ---- in-place normalization of this CTA's att rows ----
    // __syncthreads orders all prior global E-writes CTA-wide; the region
    // was never read before, so no stale L1 lines; reads mostly hit L2.
    __syncthreads();
    const int width = nkt * 128;
    #pragma unroll 1
    for (int rg = 0; rg < 16; rg++) {
        const int r = rg * 8 + wid;
        const float inv = smf[r];
        float* p = attp + (size_t)r * Tn;
        for (int c = lane * 4; c < width; c += 128) {
            float4 v = *(float4*)(p + c);
            v.x *= inv; v.y *= inv; v.z *= inv; v.w *= inv;
            *(float4*)(p + c) = v;
        }
    }
}

// ---------------------------------------------------------------------------
extern "C" void kernel_launch(void* const* d_in, const int* in_sizes, int n_in,
                              void* d_out, int out_size)
{
    const float* x  = (const float*)d_in[0];
    const float* Wq = (const float*)d_in[1];
    const float* bq = (const float*)d_in[2];
    const float* Wk = (const float*)d_in[3];
    const float* bk = (const float*)d_in[4];
    const float* Wv = (const float*)d_in[5];
    const float* bv = (const float*)d_in[6];
    const float* Wp = (const float*)d_in[7];
    const float* bp = (const float*)d_in[8];

    float* y_out   = (float*)d_out;                       // [B,T,C]
    float* att_out = y_out + (size_t)BT * Cn;             // [B,H,T,T]

    cudaFuncSetAttribute(gemm_qkv_tc,  cudaFuncAttributeMaxDynamicSharedMemorySize, GEMM_SMEM);
    cudaFuncSetAttribute(gemm_proj_tc, cudaFuncAttributeMaxDynamicSharedMemorySize, GEMM_SMEM);
    cudaFuncSetAttribute(attn_mma,     cudaFuncAttributeMaxDynamicSharedMemorySize, ATT_SMEM);

    // pre-split x and weights to bf16 hi/lo (one kernel)
    conv_all<<<8192 + 4096, 256>>>((const float4*)x, (const float4*)Wq,
                                   (const float4*)Wk, (const float4*)Wv,
                                   (const float4*)Wp);

    // QKV projections -> bf16 hi/lo q,k,v (q pre-scaled 1/8)
    gemm_qkv_tc<<<dim3(8, 64, 3), 256, GEMM_SMEM>>>(bq, bk, bv);

    // Fused MMA attention: E -> att, y = E@V / l, in-place att normalization
    attn_mma<<<dim3(NQT, Bn * Hn), 256, ATT_SMEM>>>(att_out);

    // Output projection
    gemm_proj_tc<<<dim3(8, 64), 256, GEMM_SMEM>>>(bp, y_out);
}

// round 13
// speedup vs baseline: 1.6277x; 1.1178x over previous
#include <cuda_runtime.h>
#include <cuda_bf16.h>
#include <math_constants.h>
#include <cstdint>

#define Bn 4
#define Tn 2048
#define Cn 1024
#define Hn 16
#define Dn 64
#define BT (Bn*Tn)      // 8192
#define NQT (Tn/128)    // 16 q-tiles of 128

typedef unsigned short ushort_t;

// Scratch (device globals — no allocation allowed)
__device__ __align__(16) ushort_t g_qh[(size_t)64*Tn*Dn];   // bf16 hi/lo of q (pre-scaled 0.125)
__device__ __align__(16) ushort_t g_ql[(size_t)64*Tn*Dn];
__device__ __align__(16) ushort_t g_kh[(size_t)64*Tn*Dn];
__device__ __align__(16) ushort_t g_kl[(size_t)64*Tn*Dn];
__device__ __align__(16) ushort_t g_vh[(size_t)64*Tn*Dn];
__device__ __align__(16) ushort_t g_vl[(size_t)64*Tn*Dn];
__device__ __align__(16) ushort_t g_xh[(size_t)BT*Cn];      // x pre-split
__device__ __align__(16) ushort_t g_xl[(size_t)BT*Cn];
__device__ __align__(16) ushort_t g_wh[(size_t)4*Cn*Cn];    // Wq,Wk,Wv,Wp pre-split
__device__ __align__(16) ushort_t g_wl[(size_t)4*Cn*Cn];
__device__ __align__(16) ushort_t g_yh[(size_t)BT*Cn];      // attention out (normalized), pre-split
__device__ __align__(16) ushort_t g_yl[(size_t)BT*Cn];
__device__ float g_lsum[(size_t)64*Tn];                     // softmax row sums (131072 rows)

// ---------------------------------------------------------------------------
// helpers
// ---------------------------------------------------------------------------
__device__ __forceinline__ uint32_t smem_u32(const void* p) {
    uint32_t a;
    asm("{ .reg .u64 t; cvta.to.shared.u64 t, %1; cvt.u32.u64 %0, t; }"
        : "=r"(a) : "l"(p));
    return a;
}

__device__ __forceinline__ void split2(float f0, float f1, uint32_t& hi, uint32_t& lo) {
    __nv_bfloat16 h0 = __float2bfloat16(f0);
    __nv_bfloat16 h1 = __float2bfloat16(f1);
    __nv_bfloat16 l0 = __float2bfloat16(f0 - __bfloat162float(h0));
    __nv_bfloat16 l1 = __float2bfloat16(f1 - __bfloat162float(h1));
    hi = (uint32_t)__bfloat16_as_ushort(h0) | ((uint32_t)__bfloat16_as_ushort(h1) << 16);
    lo = (uint32_t)__bfloat16_as_ushort(l0) | ((uint32_t)__bfloat16_as_ushort(l1) << 16);
}

__device__ __forceinline__ void ldm_x4(uint32_t r[4], uint32_t addr) {
    asm volatile("ldmatrix.sync.aligned.m8n8.x4.shared.b16 {%0,%1,%2,%3}, [%4];"
        : "=r"(r[0]), "=r"(r[1]), "=r"(r[2]), "=r"(r[3]) : "r"(addr));
}

__device__ __forceinline__ void ldm_x4_t(uint32_t r[4], uint32_t addr) {
    asm volatile("ldmatrix.sync.aligned.m8n8.x4.trans.shared.b16 {%0,%1,%2,%3}, [%4];"
        : "=r"(r[0]), "=r"(r[1]), "=r"(r[2]), "=r"(r[3]) : "r"(addr));
}

__device__ __forceinline__ void mma_bf16(float d[4], const uint32_t a[4], const uint32_t b[2]) {
    asm volatile(
        "mma.sync.aligned.m16n8k16.row.col.f32.bf16.bf16.f32 "
        "{%0,%1,%2,%3}, {%4,%5,%6,%7}, {%8,%9}, {%0,%1,%2,%3};"
        : "+f"(d[0]), "+f"(d[1]), "+f"(d[2]), "+f"(d[3])
        : "r"(a[0]), "r"(a[1]), "r"(a[2]), "r"(a[3]), "r"(b[0]), "r"(b[1]));
}

#define CP16(dst, src) asm volatile("cp.async.cg.shared.global [%0], [%1], 16;" :: "r"(dst), "l"(src))
#define CPCOMMIT()     asm volatile("cp.async.commit_group;" ::: "memory")
#define CPWAIT0()      asm volatile("cp.async.wait_group 0;" ::: "memory")
#define CPWAIT1()      asm volatile("cp.async.wait_group 1;" ::: "memory")

// ---------------------------------------------------------------------------
// combined pre-convert kernel: fp32 -> bf16 hi/lo for x and all 4 weights
// ---------------------------------------------------------------------------
__global__ __launch_bounds__(256) void conv_all(
    const float4* __restrict__ x,
    const float4* __restrict__ Wq, const float4* __restrict__ Wk,
    const float4* __restrict__ Wv, const float4* __restrict__ Wp)
{
    int b = blockIdx.x;
    const float4* src;
    uint2 *dh, *dl;
    int i;
    if (b < 8192) {               // x: 2M float4
        i = b * 256 + threadIdx.x;
        src = x; dh = (uint2*)g_xh; dl = (uint2*)g_xl;
    } else {                      // weights: 4 x 256K float4
        b -= 8192;
        const int z = b >> 10;
        src = (z == 0) ? Wq : (z == 1) ? Wk : (z == 2) ? Wv : Wp;
        dh = (uint2*)(g_wh + (size_t)z * Cn * Cn);
        dl = (uint2*)(g_wl + (size_t)z * Cn * Cn);
        i = (b & 1023) * 256 + threadIdx.x;
    }
    float4 v = src[i];
    uint32_t h0, l0, h1, l1;
    split2(v.x, v.y, h0, l0);
    split2(v.z, v.w, h1, l1);
    dh[i] = make_uint2(h0, h1);
    dl[i] = make_uint2(l0, l1);
}

// ===========================================================================
// bf16 pre-split GEMM, cp.async 3-stage, CTA 128x128, warp tile 64x32
// (8 warps: 2m x 4n), ~120 regs -> 2 CTAs/SM.  (R8, unchanged)
// ===========================================================================
#define GSTG 37888
#define GEMM_SMEM (3*GSTG)   // 113664

__device__ __forceinline__ void gemm_issue(
    uint32_t sbase,
    const ushort_t* __restrict__ Ah_g, const ushort_t* __restrict__ Al_g,
    const ushort_t* __restrict__ Bh_g, const ushort_t* __restrict__ Bl_g,
    int bm, int bn, int kc, int tid)
{
    #pragma unroll
    for (int i = 0; i < 2; i++) {
        const int ia = tid + 256 * i;
        const int r = ia >> 2, c = ia & 3;
        const uint32_t dst = sbase + (uint32_t)(r * 80 + c * 16);
        const size_t src = (size_t)(bm * 128 + r) * 1024 + kc * 32 + c * 8;
        CP16(dst, Ah_g + src);
        CP16(dst + 10240, Al_g + src);
    }
    #pragma unroll
    for (int i = 0; i < 2; i++) {
        const int ib = tid + 256 * i;
        const int k = ib >> 4, c = ib & 15;
        const uint32_t dst = sbase + (uint32_t)(20480 + k * 272 + c * 16);
        const size_t src = (size_t)(kc * 32 + k) * 1024 + bn * 128 + c * 8;
        CP16(dst, Bh_g + src);
        CP16(dst + 8704, Bl_g + src);
    }
    CPCOMMIT();
}

template<bool REMAP>
__device__ __forceinline__ void gemm2_body(
    const ushort_t* __restrict__ Ah_g, const ushort_t* __restrict__ Al_g,
    const ushort_t* __restrict__ Bh_g, const ushort_t* __restrict__ Bl_g,
    const float* __restrict__ bias, float* __restrict__ out,
    ushort_t* __restrict__ outH, ushort_t* __restrict__ outL, float scl)
{
    extern __shared__ char smc[];
    const uint32_t sb = smem_u32(smc);
    const int tid = threadIdx.x, wid = tid >> 5, lane = tid & 31;
    const int bm = blockIdx.y, bn = blockIdx.x;
    const int warp_m = wid & 1;        // 64 rows each
    const int warp_n = wid >> 1;       // 32 cols each

    const int l15 = lane & 15;
    const int lhi = lane >> 4;
    const uint32_t aBase = sb + (uint32_t)((warp_m * 64 + l15) * 80 + lhi * 16);
    const uint32_t bBase = sb + 20480 + (uint32_t)(l15 * 272 + warp_n * 64 + lhi * 16);

    float d[4][4][4];
    #pragma unroll
    for (int t = 0; t < 4; t++)
        #pragma unroll
        for (int u = 0; u < 4; u++)
            #pragma unroll
            for (int v = 0; v < 4; v++) d[t][u][v] = 0.f;

    gemm_issue(sb,        Ah_g, Al_g, Bh_g, Bl_g, bm, bn, 0, tid);
    gemm_issue(sb + GSTG, Ah_g, Al_g, Bh_g, Bl_g, bm, bn, 1, tid);

    for (int kc = 0; kc < 32; kc++) {
        if (kc == 31) { CPWAIT0(); } else { CPWAIT1(); }
        __syncthreads();
        if (kc < 30)
            gemm_issue(sb + (uint32_t)(((kc + 2) % 3) * GSTG),
                       Ah_g, Al_g, Bh_g, Bl_g, bm, bn, kc + 2, tid);

        const uint32_t stgOff = (uint32_t)((kc % 3) * GSTG);

        #pragma unroll
        for (int ss = 0; ss < 2; ss++) {
            uint32_t Bh[4][2], Bl[4][2];
            #pragma unroll
            for (int gp = 0; gp < 2; gp++) {
                const uint32_t ba = bBase + stgOff + (uint32_t)(ss * 16 * 272 + gp * 32);
                uint32_t r[4];
                ldm_x4_t(r, ba);
                Bh[gp*2][0] = r[0]; Bh[gp*2][1] = r[1];
                Bh[gp*2+1][0] = r[2]; Bh[gp*2+1][1] = r[3];
                ldm_x4_t(r, ba + 8704);
                Bl[gp*2][0] = r[0]; Bl[gp*2][1] = r[1];
                Bl[gp*2+1][0] = r[2]; Bl[gp*2+1][1] = r[3];
            }
            #pragma unroll
            for (int t = 0; t < 4; t++) {
                uint32_t Ah[4], Al_[4];
                const uint32_t aa = aBase + stgOff + (uint32_t)(t * 16 * 80 + ss * 32);
                ldm_x4(Ah, aa);
                ldm_x4(Al_, aa + 10240);
                #pragma unroll
                for (int u = 0; u < 4; u++) {
                    mma_bf16(d[t][u], Ah, Bh[u]);
                    mma_bf16(d[t][u], Ah, Bl[u]);
                    mma_bf16(d[t][u], Al_, Bh[u]);
                }
            }
        }
    }

    // ---- epilogue ----
    #pragma unroll
    for (int t = 0; t < 4; t++) {
        const int rowA = bm * 128 + warp_m * 64 + t * 16 + (lane >> 2);
        #pragma unroll
        for (int half = 0; half < 2; half++) {
            const int m = rowA + half * 8;
            #pragma unroll
            for (int u = 0; u < 4; u++) {
                const int col = bn * 128 + warp_n * 32 + u * 8 + ((lane & 3) << 1);
                const float v0 = d[t][u][half * 2 + 0] + __ldg(&bias[col]);
                const float v1 = d[t][u][half * 2 + 1] + __ldg(&bias[col + 1]);
                if (REMAP) {
                    const int b = m >> 11, tt = m & 2047;
                    const int h = col >> 6, d0 = col & 63;
                    const size_t idx = (((size_t)(b * Hn + h) * Tn) + tt) * Dn + d0;
                    uint32_t hh, ll;
                    split2(v0 * scl, v1 * scl, hh, ll);
                    *(uint32_t*)(outH + idx) = hh;
                    *(uint32_t*)(outL + idx) = ll;
                } else {
                    *(float2*)(out + (size_t)m * 1024 + col) = make_float2(v0, v1);
                }
            }
        }
    }
}

__global__ __launch_bounds__(256, 2) void gemm_qkv_tc(
    const float* __restrict__ bq, const float* __restrict__ bk,
    const float* __restrict__ bv)
{
    const float* bias; ushort_t *oh, *ol; float scl;
    if (blockIdx.z == 0)      { bias = bq; oh = g_qh; ol = g_ql; scl = 0.125f; }
    else if (blockIdx.z == 1) { bias = bk; oh = g_kh; ol = g_kl; scl = 1.f; }
    else                      { bias = bv; oh = g_vh; ol = g_vl; scl = 1.f; }
    const size_t wo = (size_t)blockIdx.z * Cn * Cn;
    gemm2_body<true>(g_xh, g_xl, g_wh + wo, g_wl + wo, bias, nullptr, oh, ol, scl);
}

__global__ __launch_bounds__(256, 2) void gemm_proj_tc(
    const float* __restrict__ bp, float* __restrict__ out)
{
    const size_t wo = (size_t)3 * Cn * Cn;
    gemm2_body<false>(g_yh, g_yl, g_wh + wo, g_wl + wo, bp, out, nullptr, nullptr, 1.f);
}

// ===========================================================================
// MMA attention, 512 threads / 16 warps: warp (qg, kh) owns 16 q-rows x 64
// keys.  Halved per-warp state (-> no spill at 128-reg cap), 4 warps/SMSP.
// Partial y and row sums combined warp-pair-wise via SMEM at the end.
// ===========================================================================
#define ATT_SMEM 131072
#define AKH 0
#define AKL 16384
#define AVH 32768
#define AVL 49152

__global__ __launch_bounds__(512, 1) void attn_mma(float* __restrict__ att)
{
    extern __shared__ char smc[];
    const uint32_t sb = smem_u32(smc);
    const int tid = threadIdx.x, wid = tid >> 5, lane = tid & 31;
    const int qg = wid & 7;          // q-row group (16 rows)
    const int kh = wid >> 3;         // key half (64 keys)
    const int bh = blockIdx.y;
    const int qt = (NQT - 1) - blockIdx.x;
    const int qbase = qt * 128;
    const int nkt = qt + 1;

    const ushort_t* qh = g_qh + ((size_t)bh * Tn + qbase) * Dn;
    const ushort_t* ql = g_ql + ((size_t)bh * Tn + qbase) * Dn;
    const ushort_t* khp = g_kh + (size_t)bh * Tn * Dn;
    const ushort_t* klp = g_kl + (size_t)bh * Tn * Dn;
    const ushort_t* vhp = g_vh + (size_t)bh * Tn * Dn;
    const ushort_t* vlp = g_vl + (size_t)bh * Tn * Dn;
    float* attp = att + ((size_t)bh * Tn + qbase) * Tn;

    // Q stage into buffer0
    #pragma unroll
    for (int i = 0; i < 2; i++) {
        const int idx = tid + 512 * i;
        const int r = idx >> 3, c = idx & 7;
        const uint32_t off = (uint32_t)(r * 128 + ((c ^ (r & 7)) << 4));
        CP16(sb + AKH + off, qh + r * 64 + c * 8);
        CP16(sb + AKL + off, ql + r * 64 + c * 8);
    }
    CPCOMMIT();

    // K/V tile 0 into buffer1
    {
        const uint32_t base = sb + 65536;
        #pragma unroll
        for (int i = 0; i < 2; i++) {
            const int idx = tid + 512 * i;
            const int r = idx >> 3, c = idx & 7;
            const uint32_t off = (uint32_t)(r * 128 + ((c ^ (r & 7)) << 4));
            const size_t so = (size_t)r * 64 + c * 8;
            CP16(base + AKH + off, khp + so);
            CP16(base + AKL + off, klp + so);
            CP16(base + AVH + off, vhp + so);
            CP16(base + AVL + off, vlp + so);
        }
        CPCOMMIT();
    }

    // zero-fill strict-upper tiles while the async loads fly
    const int zstart = nkt * 128;
    #pragma unroll 1
    for (int rg = 0; rg < 8; rg++) {
        const int r = rg * 16 + wid;
        for (int c = zstart + lane * 4; c < Tn; c += 128)
            *(float4*)(attp + (size_t)r * Tn + c) = make_float4(0.f, 0.f, 0.f, 0.f);
    }

    CPWAIT1();
    __syncthreads();

    // Q fragments (same rows for both kh halves of a pair)
    uint32_t q_h[4][4], q_l[4][4];
    {
        const int arow = 16 * qg + ((lane >> 3) & 1) * 8 + (lane & 7);
        #pragma unroll
        for (int kk = 0; kk < 4; kk++) {
            const uint32_t addr = sb + AKH + (uint32_t)(arow * 128 +
                (((2 * kk + (lane >> 4)) ^ (arow & 7)) << 4));
            ldm_x4(q_h[kk], addr);
            ldm_x4(q_l[kk], addr + 16384);
        }
    }
    __syncthreads();

    const int bkeyL = ((lane >> 4) << 3) + (lane & 7);
    const int bchk  = (lane >> 3) & 1;
    const uint32_t brow = (uint32_t)(bkeyL * 128);
    const int bsw = bkeyL & 7;

    const int vkeyL = ((lane >> 3) & 1) * 8 + (lane & 7);
    const int vchk  = lane >> 4;
    const uint32_t vrow = (uint32_t)(vkeyL * 128);
    const int vsw = vkeyL & 7;

    const int rl0 = 16 * qg + (lane >> 2);
    const int cl0 = 2 * (lane & 3);
    const int kcolbase = kh * 64;    // this warp's key-column offset in tile

    float d_y[8][4];
    #pragma unroll
    for (int j = 0; j < 8; j++)
        #pragma unroll
        for (int v = 0; v < 4; v++) d_y[j][v] = 0.f;
    float lsum0 = 0.f, lsum1 = 0.f;

    for (int kt = 0; kt < nkt; kt++) {
        const int buf = (kt + 1) & 1;
        if (kt + 1 < nkt) {
            const uint32_t base = sb + (uint32_t)((kt & 1) * 65536);
            const size_t tof = (size_t)(kt + 1) * 128 * 64;
            #pragma unroll
            for (int i = 0; i < 2; i++) {
                const int idx = tid + 512 * i;
                const int r = idx >> 3, c = idx & 7;
                const uint32_t off = (uint32_t)(r * 128 + ((c ^ (r & 7)) << 4));
                const size_t so = tof + (size_t)r * 64 + c * 8;
                CP16(base + AKH + off, khp + so);
                CP16(base + AKL + off, klp + so);
                CP16(base + AVH + off, vhp + so);
                CP16(base + AVL + off, vlp + so);
            }
            CPCOMMIT();
            CPWAIT1();
        } else {
            CPWAIT0();
        }
        __syncthreads();

        const uint32_t base = sb + (uint32_t)(buf * 65536);

        // ---- S = Q @ K^T for this warp's 64 keys (3-term) ----
        float ds[8][4];
        #pragma unroll
        for (int j = 0; j < 8; j++)
            #pragma unroll
            for (int v = 0; v < 4; v++) ds[j][v] = 0.f;

        #pragma unroll
        for (int kk = 0; kk < 4; kk++) {
            #pragma unroll
            for (int j16 = 0; j16 < 4; j16++) {
                const int jg = kh * 4 + j16;
                const uint32_t ka = base + AKH + (uint32_t)(jg * 2048) + brow +
                                    (uint32_t)((((kk << 1) | bchk) ^ bsw) << 4);
                uint32_t khf[4], klf[4];
                ldm_x4(khf, ka);
                ldm_x4(klf, ka + 16384);
                uint32_t b0h[2] = {khf[0], khf[1]}, b1h[2] = {khf[2], khf[3]};
                uint32_t b0l[2] = {klf[0], klf[1]}, b1l[2] = {klf[2], klf[3]};
                mma_bf16(ds[2*j16],   q_h[kk], b0h);
                mma_bf16(ds[2*j16],   q_h[kk], b0l);
                mma_bf16(ds[2*j16],   q_l[kk], b0h);
                mma_bf16(ds[2*j16+1], q_h[kk], b1h);
                mma_bf16(ds[2*j16+1], q_h[kk], b1l);
                mma_bf16(ds[2*j16+1], q_l[kk], b1h);
            }
        }

        // ---- exp, causal mask, att store, partial row sums ----
        const bool diag = (kt == qt);
        const int ktbase = kt * 128;
        #pragma unroll
        for (int j = 0; j < 8; j++) {
            const int c = kcolbase + 8 * j + cl0;   // tile-local col
            float e00 = __expf(ds[j][0]);
            float e01 = __expf(ds[j][1]);
            float e10 = __expf(ds[j][2]);
            float e11 = __expf(ds[j][3]);
            if (diag) {
                if (c     > rl0)     e00 = 0.f;
                if (c + 1 > rl0)     e01 = 0.f;
                if (c     > rl0 + 8) e10 = 0.f;
                if (c + 1 > rl0 + 8) e11 = 0.f;
            }
            ds[j][0] = e00; ds[j][1] = e01; ds[j][2] = e10; ds[j][3] = e11;
            *(float2*)(attp + (size_t)rl0 * Tn + ktbase + c)       = make_float2(e00, e01);
            *(float2*)(attp + (size_t)(rl0 + 8) * Tn + ktbase + c) = make_float2(e10, e11);
            lsum0 += e00 + e01;
            lsum1 += e10 + e11;
        }

        // ---- partial Y += P @ V over this warp's 64 keys (3-term) ----
        #pragma unroll
        for (int kap = 0; kap < 4; kap++) {
            uint32_t p_h[4], p_l[4];
            split2(ds[2*kap][0],   ds[2*kap][1],   p_h[0], p_l[0]);
            split2(ds[2*kap][2],   ds[2*kap][3],   p_h[1], p_l[1]);
            split2(ds[2*kap+1][0], ds[2*kap+1][1], p_h[2], p_l[2]);
            split2(ds[2*kap+1][2], ds[2*kap+1][3], p_h[3], p_l[3]);
            const int kgl = kh * 4 + kap;
            #pragma unroll
            for (int j16 = 0; j16 < 4; j16++) {
                const uint32_t va = base + AVH + (uint32_t)(kgl * 2048) + vrow +
                                    (uint32_t)((((j16 << 1) | vchk) ^ vsw) << 4);
                uint32_t vhf[4], vlf[4];
                ldm_x4_t(vhf, va);
                ldm_x4_t(vlf, va + 16384);
                uint32_t v0h[2] = {vhf[0], vhf[1]}, v1h[2] = {vhf[2], vhf[3]};
                uint32_t v0l[2] = {vlf[0], vlf[1]}, v1l[2] = {vlf[2], vlf[3]};
                mma_bf16(d_y[2*j16],   p_h, v0h);
                mma_bf16(d_y[2*j16],   p_h, v0l);
                mma_bf16(d_y[2*j16],   p_l, v0h);
                mma_bf16(d_y[2*j16+1], p_h, v1h);
                mma_bf16(d_y[2*j16+1], p_h, v1l);
                mma_bf16(d_y[2*j16+1], p_l, v1h);
            }
        }
        __syncthreads();
    }

    // ---- reduce partial lsums within quad ----
    lsum0 += __shfl_xor_sync(0xffffffffu, lsum0, 1);
    lsum0 += __shfl_xor_sync(0xffffffffu, lsum0, 2);
    lsum1 += __shfl_xor_sync(0xffffffffu, lsum1, 1);
    lsum1 += __shfl_xor_sync(0xffffffffu, lsum1, 2);

    // ---- combine warp pairs (kh=1 -> SMEM -> kh=0) ----
    float* smf = (float*)smc;               // KV buffers are dead now
    #define YEX(qg_, lane_, j_) ((qg_) * 1056 + (lane_) * 33 + (j_))
    #define LSX(qg_, r_)        (8448 + (qg_) * 16 + (r_))
    __syncthreads();
    if (kh == 1) {
        #pragma unroll
        for (int j = 0; j < 8; j++)
            #pragma unroll
            for (int v = 0; v < 4; v++)
                smf[YEX(qg, lane, j * 4 + v)] = d_y[j][v];
        if ((lane & 3) == 0) {
            smf[LSX(qg, (lane >> 2))]     = lsum0;
            smf[LSX(qg, (lane >> 2) + 8)] = lsum1;
        }
    }
    __syncthreads();
    if (kh == 0) {
        #pragma unroll
        for (int j = 0; j < 8; j++)
            #pragma unroll
            for (int v = 0; v < 4; v++)
                d_y[j][v] += smf[YEX(qg, lane, j * 4 + v)];
        lsum0 += smf[LSX(qg, (lane >> 2))];
        lsum1 += smf[LSX(qg, (lane >> 2) + 8)];

        const float inv0 = 1.f / lsum0;
        const float inv1 = 1.f / lsum1;
        if ((lane & 3) == 0) {
            g_lsum[(size_t)bh * Tn + qbase + rl0]     = lsum0;
            g_lsum[(size_t)bh * Tn + qbase + rl0 + 8] = lsum1;
        }
        const int b = bh >> 4, hh = bh & 15;
        const size_t y0i = ((size_t)(b * Tn + qbase + rl0)) * Cn + hh * 64;
        const size_t y1i = y0i + (size_t)8 * Cn;
        #pragma unroll
        for (int j = 0; j < 8; j++) {
            uint32_t h, l;
            split2(d_y[j][0] * inv0, d_y[j][1] * inv0, h, l);
            *(uint32_t*)(g_yh + y0i + 8 * j + cl0) = h;
            *(uint32_t*)(g_yl + y0i + 8 * j + cl0) = l;
            split2(d_y[j][2] * inv1, d_y[j][3] * inv1, h, l);
            *(uint32_t*)(g_yh + y1i + 8 * j + cl0) = h;
            *(uint32_t*)(g_yl + y1i + 8 * j + cl0) = l;
        }
    }
}

// ---------------------------------------------------------------------------
// Normalize att rows by 1/l (lower-triangle region only). Warp per row. (R8)
// ---------------------------------------------------------------------------
__global__ __launch_bounds__(256) void norm_att(float* __restrict__ att)
{
    const int wid = threadIdx.x >> 5, lane = threadIdx.x & 31;
    const size_t row = (size_t)blockIdx.x * 8 + wid;
    const int rs = (int)(row & (Tn - 1));
    const int width = ((rs >> 7) + 1) * 128;
    const float inv = 1.f / g_lsum[row];
    float* p = att + row * Tn;
    for (int c = lane * 4; c < width; c += 128) {
        float4 v = *(float4*)(p + c);
        v.x *= inv; v.y *= inv; v.z *= inv; v.w *= inv;
        *(float4*)(p + c) = v;
    }
}

// ---------------------------------------------------------------------------
extern "C" void kernel_launch(void* const* d_in, const int* in_sizes, int n_in,
                              void* d_out, int out_size)
{
    const float* x  = (const float*)d_in[0];
    const float* Wq = (const float*)d_in[1];
    const float* bq = (const float*)d_in[2];
    const float* Wk = (const float*)d_in[3];
    const float* bk = (const float*)d_in[4];
    const float* Wv = (const float*)d_in[5];
    const float* bv = (const float*)d_in[6];
    const float* Wp = (const float*)d_in[7];
    const float* bp = (const float*)d_in[8];

    float* y_out   = (float*)d_out;                       // [B,T,C]
    float* att_out = y_out + (size_t)BT * Cn;             // [B,H,T,T]

    cudaFuncSetAttribute(gemm_qkv_tc,  cudaFuncAttributeMaxDynamicSharedMemorySize, GEMM_SMEM);
    cudaFuncSetAttribute(gemm_proj_tc, cudaFuncAttributeMaxDynamicSharedMemorySize, GEMM_SMEM);
    cudaFuncSetAttribute(attn_mma,     cudaFuncAttributeMaxDynamicSharedMemorySize, ATT_SMEM);

    // pre-split x and weights to bf16 hi/lo (one kernel)
    conv_all<<<8192 + 4096, 256>>>((const float4*)x, (const float4*)Wq,
                                   (const float4*)Wk, (const float4*)Wv,
                                   (const float4*)Wp);

    // QKV projections -> bf16 hi/lo q,k,v (q pre-scaled 1/8)
    gemm_qkv_tc<<<dim3(8, 64, 3), 256, GEMM_SMEM>>>(bq, bk, bv);

    // Fused MMA attention (512 thr, split-K warps): E -> att, y = E@V / l
    attn_mma<<<dim3(NQT, Bn * Hn), 512, ATT_SMEM>>>(att_out);

    // Normalize att lower triangle by 1/l
    norm_att<<<(64 * Tn) / 8, 256>>>(att_out);

    // Output projection
    gemm_proj_tc<<<dim3(8, 64), 256, GEMM_SMEM>>>(bp, y_out);
}

// round 14
// speedup vs baseline: 1.6414x; 1.0084x over previous
#include <cuda_runtime.h>
#include <cuda_bf16.h>
#include <math_constants.h>
#include <cstdint>

#define Bn 4
#define Tn 2048
#define Cn 1024
#define Hn 16
#define Dn 64
#define BT (Bn*Tn)      // 8192
#define NQT (Tn/128)    // 16 q-tiles of 128

typedef unsigned short ushort_t;

// Scratch (device globals — no allocation allowed)
__device__ __align__(16) ushort_t g_qh[(size_t)64*Tn*Dn];   // bf16 hi/lo of q (pre-scaled 0.125)
__device__ __align__(16) ushort_t g_ql[(size_t)64*Tn*Dn];
__device__ __align__(16) ushort_t g_kh[(size_t)64*Tn*Dn];
__device__ __align__(16) ushort_t g_kl[(size_t)64*Tn*Dn];
__device__ __align__(16) ushort_t g_vh[(size_t)64*Tn*Dn];
__device__ __align__(16) ushort_t g_vl[(size_t)64*Tn*Dn];
__device__ __align__(16) ushort_t g_xh[(size_t)BT*Cn];      // x pre-split
__device__ __align__(16) ushort_t g_xl[(size_t)BT*Cn];
__device__ __align__(16) ushort_t g_wh[(size_t)4*Cn*Cn];    // Wq,Wk,Wv,Wp pre-split
__device__ __align__(16) ushort_t g_wl[(size_t)4*Cn*Cn];
__device__ __align__(16) ushort_t g_yh[(size_t)BT*Cn];      // attention out (normalized), pre-split
__device__ __align__(16) ushort_t g_yl[(size_t)BT*Cn];
__device__ float g_lsum[(size_t)64*Tn];                     // softmax row sums (131072 rows)

// ---------------------------------------------------------------------------
// helpers
// ---------------------------------------------------------------------------
__device__ __forceinline__ uint32_t smem_u32(const void* p) {
    uint32_t a;
    asm("{ .reg .u64 t; cvta.to.shared.u64 t, %1; cvt.u32.u64 %0, t; }"
        : "=r"(a) : "l"(p));
    return a;
}

__device__ __forceinline__ void split2(float f0, float f1, uint32_t& hi, uint32_t& lo) {
    __nv_bfloat16 h0 = __float2bfloat16(f0);
    __nv_bfloat16 h1 = __float2bfloat16(f1);
    __nv_bfloat16 l0 = __float2bfloat16(f0 - __bfloat162float(h0));
    __nv_bfloat16 l1 = __float2bfloat16(f1 - __bfloat162float(h1));
    hi = (uint32_t)__bfloat16_as_ushort(h0) | ((uint32_t)__bfloat16_as_ushort(h1) << 16);
    lo = (uint32_t)__bfloat16_as_ushort(l0) | ((uint32_t)__bfloat16_as_ushort(l1) << 16);
}

__device__ __forceinline__ void ldm_x4(uint32_t r[4], uint32_t addr) {
    asm volatile("ldmatrix.sync.aligned.m8n8.x4.shared.b16 {%0,%1,%2,%3}, [%4];"
        : "=r"(r[0]), "=r"(r[1]), "=r"(r[2]), "=r"(r[3]) : "r"(addr));
}

__device__ __forceinline__ void ldm_x4_t(uint32_t r[4], uint32_t addr) {
    asm volatile("ldmatrix.sync.aligned.m8n8.x4.trans.shared.b16 {%0,%1,%2,%3}, [%4];"
        : "=r"(r[0]), "=r"(r[1]), "=r"(r[2]), "=r"(r[3]) : "r"(addr));
}

__device__ __forceinline__ void mma_bf16(float d[4], const uint32_t a[4], const uint32_t b[2]) {
    asm volatile(
        "mma.sync.aligned.m16n8k16.row.col.f32.bf16.bf16.f32 "
        "{%0,%1,%2,%3}, {%4,%5,%6,%7}, {%8,%9}, {%0,%1,%2,%3};"
        : "+f"(d[0]), "+f"(d[1]), "+f"(d[2]), "+f"(d[3])
        : "r"(a[0]), "r"(a[1]), "r"(a[2]), "r"(a[3]), "r"(b[0]), "r"(b[1]));
}

#define CP16(dst, src) asm volatile("cp.async.cg.shared.global [%0], [%1], 16;" :: "r"(dst), "l"(src))
#define CPCOMMIT()     asm volatile("cp.async.commit_group;" ::: "memory")
#define CPWAIT0()      asm volatile("cp.async.wait_group 0;" ::: "memory")
#define CPWAIT1()      asm volatile("cp.async.wait_group 1;" ::: "memory")

// ---------------------------------------------------------------------------
// combined pre-convert kernel: fp32 -> bf16 hi/lo for x and all 4 weights
// ---------------------------------------------------------------------------
__global__ __launch_bounds__(256) void conv_all(
    const float4* __restrict__ x,
    const float4* __restrict__ Wq, const float4* __restrict__ Wk,
    const float4* __restrict__ Wv, const float4* __restrict__ Wp)
{
    int b = blockIdx.x;
    const float4* src;
    uint2 *dh, *dl;
    int i;
    if (b < 8192) {               // x: 2M float4
        i = b * 256 + threadIdx.x;
        src = x; dh = (uint2*)g_xh; dl = (uint2*)g_xl;
    } else {                      // weights: 4 x 256K float4
        b -= 8192;
        const int z = b >> 10;
        src = (z == 0) ? Wq : (z == 1) ? Wk : (z == 2) ? Wv : Wp;
        dh = (uint2*)(g_wh + (size_t)z * Cn * Cn);
        dl = (uint2*)(g_wl + (size_t)z * Cn * Cn);
        i = (b & 1023) * 256 + threadIdx.x;
    }
    float4 v = src[i];
    uint32_t h0, l0, h1, l1;
    split2(v.x, v.y, h0, l0);
    split2(v.z, v.w, h1, l1);
    dh[i] = make_uint2(h0, h1);
    dl[i] = make_uint2(l0, l1);
}

// ===========================================================================
// bf16 pre-split GEMM, cp.async 3-stage, CTA 128x128, warp tile 64x32
// (8 warps: 2m x 4n), ~120 regs -> 2 CTAs/SM.  (R8, unchanged)
// ===========================================================================
#define GSTG 37888
#define GEMM_SMEM (3*GSTG)   // 113664

__device__ __forceinline__ void gemm_issue(
    uint32_t sbase,
    const ushort_t* __restrict__ Ah_g, const ushort_t* __restrict__ Al_g,
    const ushort_t* __restrict__ Bh_g, const ushort_t* __restrict__ Bl_g,
    int bm, int bn, int kc, int tid)
{
    #pragma unroll
    for (int i = 0; i < 2; i++) {
        const int ia = tid + 256 * i;
        const int r = ia >> 2, c = ia & 3;
        const uint32_t dst = sbase + (uint32_t)(r * 80 + c * 16);
        const size_t src = (size_t)(bm * 128 + r) * 1024 + kc * 32 + c * 8;
        CP16(dst, Ah_g + src);
        CP16(dst + 10240, Al_g + src);
    }
    #pragma unroll
    for (int i = 0; i < 2; i++) {
        const int ib = tid + 256 * i;
        const int k = ib >> 4, c = ib & 15;
        const uint32_t dst = sbase + (uint32_t)(20480 + k * 272 + c * 16);
        const size_t src = (size_t)(kc * 32 + k) * 1024 + bn * 128 + c * 8;
        CP16(dst, Bh_g + src);
        CP16(dst + 8704, Bl_g + src);
    }
    CPCOMMIT();
}

template<bool REMAP>
__device__ __forceinline__ void gemm2_body(
    const ushort_t* __restrict__ Ah_g, const ushort_t* __restrict__ Al_g,
    const ushort_t* __restrict__ Bh_g, const ushort_t* __restrict__ Bl_g,
    const float* __restrict__ bias, float* __restrict__ out,
    ushort_t* __restrict__ outH, ushort_t* __restrict__ outL, float scl)
{
    extern __shared__ char smc[];
    const uint32_t sb = smem_u32(smc);
    const int tid = threadIdx.x, wid = tid >> 5, lane = tid & 31;
    const int bm = blockIdx.y, bn = blockIdx.x;
    const int warp_m = wid & 1;        // 64 rows each
    const int warp_n = wid >> 1;       // 32 cols each

    const int l15 = lane & 15;
    const int lhi = lane >> 4;
    const uint32_t aBase = sb + (uint32_t)((warp_m * 64 + l15) * 80 + lhi * 16);
    const uint32_t bBase = sb + 20480 + (uint32_t)(l15 * 272 + warp_n * 64 + lhi * 16);

    float d[4][4][4];
    #pragma unroll
    for (int t = 0; t < 4; t++)
        #pragma unroll
        for (int u = 0; u < 4; u++)
            #pragma unroll
            for (int v = 0; v < 4; v++) d[t][u][v] = 0.f;

    gemm_issue(sb,        Ah_g, Al_g, Bh_g, Bl_g, bm, bn, 0, tid);
    gemm_issue(sb + GSTG, Ah_g, Al_g, Bh_g, Bl_g, bm, bn, 1, tid);

    for (int kc = 0; kc < 32; kc++) {
        if (kc == 31) { CPWAIT0(); } else { CPWAIT1(); }
        __syncthreads();
        if (kc < 30)
            gemm_issue(sb + (uint32_t)(((kc + 2) % 3) * GSTG),
                       Ah_g, Al_g, Bh_g, Bl_g, bm, bn, kc + 2, tid);

        const uint32_t stgOff = (uint32_t)((kc % 3) * GSTG);

        #pragma unroll
        for (int ss = 0; ss < 2; ss++) {
            uint32_t Bh[4][2], Bl[4][2];
            #pragma unroll
            for (int gp = 0; gp < 2; gp++) {
                const uint32_t ba = bBase + stgOff + (uint32_t)(ss * 16 * 272 + gp * 32);
                uint32_t r[4];
                ldm_x4_t(r, ba);
                Bh[gp*2][0] = r[0]; Bh[gp*2][1] = r[1];
                Bh[gp*2+1][0] = r[2]; Bh[gp*2+1][1] = r[3];
                ldm_x4_t(r, ba + 8704);
                Bl[gp*2][0] = r[0]; Bl[gp*2][1] = r[1];
                Bl[gp*2+1][0] = r[2]; Bl[gp*2+1][1] = r[3];
            }
            #pragma unroll
            for (int t = 0; t < 4; t++) {
                uint32_t Ah[4], Al_[4];
                const uint32_t aa = aBase + stgOff + (uint32_t)(t * 16 * 80 + ss * 32);
                ldm_x4(Ah, aa);
                ldm_x4(Al_, aa + 10240);
                #pragma unroll
                for (int u = 0; u < 4; u++) {
                    mma_bf16(d[t][u], Ah, Bh[u]);
                    mma_bf16(d[t][u], Ah, Bl[u]);
                    mma_bf16(d[t][u], Al_, Bh[u]);
                }
            }
        }
    }

    // ---- epilogue ----
    #pragma unroll
    for (int t = 0; t < 4; t++) {
        const int rowA = bm * 128 + warp_m * 64 + t * 16 + (lane >> 2);
        #pragma unroll
        for (int half = 0; half < 2; half++) {
            const int m = rowA + half * 8;
            #pragma unroll
            for (int u = 0; u < 4; u++) {
                const int col = bn * 128 + warp_n * 32 + u * 8 + ((lane & 3) << 1);
                const float v0 = d[t][u][half * 2 + 0] + __ldg(&bias[col]);
                const float v1 = d[t][u][half * 2 + 1] + __ldg(&bias[col + 1]);
                if (REMAP) {
                    const int b = m >> 11, tt = m & 2047;
                    const int h = col >> 6, d0 = col & 63;
                    const size_t idx = (((size_t)(b * Hn + h) * Tn) + tt) * Dn + d0;
                    uint32_t hh, ll;
                    split2(v0 * scl, v1 * scl, hh, ll);
                    *(uint32_t*)(outH + idx) = hh;
                    *(uint32_t*)(outL + idx) = ll;
                } else {
                    *(float2*)(out + (size_t)m * 1024 + col) = make_float2(v0, v1);
                }
            }
        }
    }
}

__global__ __launch_bounds__(256, 2) void gemm_qkv_tc(
    const float* __restrict__ bq, const float* __restrict__ bk,
    const float* __restrict__ bv)
{
    const float* bias; ushort_t *oh, *ol; float scl;
    if (blockIdx.z == 0)      { bias = bq; oh = g_qh; ol = g_ql; scl = 0.125f; }
    else if (blockIdx.z == 1) { bias = bk; oh = g_kh; ol = g_kl; scl = 1.f; }
    else                      { bias = bv; oh = g_vh; ol = g_vl; scl = 1.f; }
    const size_t wo = (size_t)blockIdx.z * Cn * Cn;
    gemm2_body<true>(g_xh, g_xl, g_wh + wo, g_wl + wo, bias, nullptr, oh, ol, scl);
}

__global__ __launch_bounds__(256, 2) void gemm_proj_tc(
    const float* __restrict__ bp, float* __restrict__ out)
{
    const size_t wo = (size_t)3 * Cn * Cn;
    gemm2_body<false>(g_yh, g_yl, g_wh + wo, g_wl + wo, bp, out, nullptr, nullptr, 1.f);
}

// ===========================================================================
// MMA attention (R8, unchanged): single pass, unnormalized E -> att,
// y = E@V / l written as bf16 hi/lo.
// ===========================================================================
#define ATT_SMEM 131072
#define AKH 0
#define AKL 16384
#define AVH 32768
#define AVL 49152

__global__ __launch_bounds__(256, 1) void attn_mma(float* __restrict__ att)
{
    extern __shared__ char smc[];
    const uint32_t sb = smem_u32(smc);
    const int tid = threadIdx.x, wid = tid >> 5, lane = tid & 31;
    const int bh = blockIdx.y;
    const int qt = (NQT - 1) - blockIdx.x;
    const int qbase = qt * 128;
    const int nkt = qt + 1;

    const ushort_t* qh = g_qh + ((size_t)bh * Tn + qbase) * Dn;
    const ushort_t* ql = g_ql + ((size_t)bh * Tn + qbase) * Dn;
    const ushort_t* khp = g_kh + (size_t)bh * Tn * Dn;
    const ushort_t* klp = g_kl + (size_t)bh * Tn * Dn;
    const ushort_t* vhp = g_vh + (size_t)bh * Tn * Dn;
    const ushort_t* vlp = g_vl + (size_t)bh * Tn * Dn;
    float* attp = att + ((size_t)bh * Tn + qbase) * Tn;

    // Q stage into buffer0
    #pragma unroll
    for (int i = 0; i < 4; i++) {
        const int idx = tid + 256 * i;
        const int r = idx >> 3, c = idx & 7;
        const uint32_t off = (uint32_t)(r * 128 + ((c ^ (r & 7)) << 4));
        CP16(sb + AKH + off, qh + r * 64 + c * 8);
        CP16(sb + AKL + off, ql + r * 64 + c * 8);
    }
    CPCOMMIT();

    // K/V tile 0 into buffer1
    {
        const uint32_t base = sb + 65536;
        #pragma unroll
        for (int i = 0; i < 4; i++) {
            const int idx = tid + 256 * i;
            const int r = idx >> 3, c = idx & 7;
            const uint32_t off = (uint32_t)(r * 128 + ((c ^ (r & 7)) << 4));
            const size_t so = (size_t)r * 64 + c * 8;
            CP16(base + AKH + off, khp + so);
            CP16(base + AKL + off, klp + so);
            CP16(base + AVH + off, vhp + so);
            CP16(base + AVL + off, vlp + so);
        }
        CPCOMMIT();
    }

    // zero-fill strict-upper tiles while the async loads fly
    const int zstart = nkt * 128;
    #pragma unroll 1
    for (int rg = 0; rg < 16; rg++) {
        const int r = rg * 8 + wid;
        for (int c = zstart + lane * 4; c < Tn; c += 128)
            *(float4*)(attp + (size_t)r * Tn + c) = make_float4(0.f, 0.f, 0.f, 0.f);
    }

    CPWAIT1();
    __syncthreads();

    uint32_t q_h[4][4], q_l[4][4];
    {
        const int arow = 16 * wid + ((lane >> 3) & 1) * 8 + (lane & 7);
        #pragma unroll
        for (int kk = 0; kk < 4; kk++) {
            const uint32_t addr = sb + AKH + (uint32_t)(arow * 128 +
                (((2 * kk + (lane >> 4)) ^ (arow & 7)) << 4));
            ldm_x4(q_h[kk], addr);
            ldm_x4(q_l[kk], addr + 16384);
        }
    }
    __syncthreads();

    const int bkeyL = ((lane >> 4) << 3) + (lane & 7);
    const int bchk  = (lane >> 3) & 1;
    const uint32_t brow = (uint32_t)(bkeyL * 128);
    const int bsw = bkeyL & 7;

    const int vkeyL = ((lane >> 3) & 1) * 8 + (lane & 7);
    const int vchk  = lane >> 4;
    const uint32_t vrow = (uint32_t)(vkeyL * 128);
    const int vsw = vkeyL & 7;

    const int rl0 = 16 * wid + (lane >> 2);
    const int cl0 = 2 * (lane & 3);

    float d_y[8][4];
    #pragma unroll
    for (int j = 0; j < 8; j++)
        #pragma unroll
        for (int v = 0; v < 4; v++) d_y[j][v] = 0.f;
    float lsum0 = 0.f, lsum1 = 0.f;

    for (int kt = 0; kt < nkt; kt++) {
        const int buf = (kt + 1) & 1;
        if (kt + 1 < nkt) {
            const uint32_t base = sb + (uint32_t)((kt & 1) * 65536);
            const size_t tof = (size_t)(kt + 1) * 128 * 64;
            #pragma unroll
            for (int i = 0; i < 4; i++) {
                const int idx = tid + 256 * i;
                const int r = idx >> 3, c = idx & 7;
                const uint32_t off = (uint32_t)(r * 128 + ((c ^ (r & 7)) << 4));
                const size_t so = tof + (size_t)r * 64 + c * 8;
                CP16(base + AKH + off, khp + so);
                CP16(base + AKL + off, klp + so);
                CP16(base + AVH + off, vhp + so);
                CP16(base + AVL + off, vlp + so);
            }
            CPCOMMIT();
            CPWAIT1();
        } else {
            CPWAIT0();
        }
        __syncthreads();

        const uint32_t base = sb + (uint32_t)(buf * 65536);

        float ds[16][4];
        #pragma unroll
        for (int j = 0; j < 16; j++)
            #pragma unroll
            for (int v = 0; v < 4; v++) ds[j][v] = 0.f;

        #pragma unroll
        for (int kk = 0; kk < 4; kk++) {
            #pragma unroll
            for (int j16 = 0; j16 < 8; j16++) {
                const uint32_t ka = base + AKH + (uint32_t)(j16 * 2048) + brow +
                                    (uint32_t)((((kk << 1) | bchk) ^ bsw) << 4);
                uint32_t khf[4], klf[4];
                ldm_x4(khf, ka);
                ldm_x4(klf, ka + 16384);
                uint32_t b0h[2] = {khf[0], khf[1]}, b1h[2] = {khf[2], khf[3]};
                uint32_t b0l[2] = {klf[0], klf[1]}, b1l[2] = {klf[2], klf[3]};
                mma_bf16(ds[2*j16],   q_h[kk], b0h);
                mma_bf16(ds[2*j16],   q_h[kk], b0l);
                mma_bf16(ds[2*j16],   q_l[kk], b0h);
                mma_bf16(ds[2*j16+1], q_h[kk], b1h);
                mma_bf16(ds[2*j16+1], q_h[kk], b1l);
                mma_bf16(ds[2*j16+1], q_l[kk], b1h);
            }
        }

        const bool diag = (kt == qt);
        const int ktbase = kt * 128;
        #pragma unroll
        for (int j = 0; j < 16; j++) {
            const int c = 8 * j + cl0;
            float e00 = __expf(ds[j][0]);
            float e01 = __expf(ds[j][1]);
            float e10 = __expf(ds[j][2]);
            float e11 = __expf(ds[j][3]);
            if (diag) {
                if (c     > rl0)     e00 = 0.f;
                if (c + 1 > rl0)     e01 = 0.f;
                if (c     > rl0 + 8) e10 = 0.f;
                if (c + 1 > rl0 + 8) e11 = 0.f;
            }
            ds[j][0] = e00; ds[j][1] = e01; ds[j][2] = e10; ds[j][3] = e11;
            *(float2*)(attp + (size_t)rl0 * Tn + ktbase + c)       = make_float2(e00, e01);
            *(float2*)(attp + (size_t)(rl0 + 8) * Tn + ktbase + c) = make_float2(e10, e11);
            lsum0 += e00 + e01;
            lsum1 += e10 + e11;
        }

        #pragma unroll
        for (int kap = 0; kap < 8; kap++) {
            uint32_t p_h[4], p_l[4];
            split2(ds[2*kap][0],   ds[2*kap][1],   p_h[0], p_l[0]);
            split2(ds[2*kap][2],   ds[2*kap][3],   p_h[1], p_l[1]);
            split2(ds[2*kap+1][0], ds[2*kap+1][1], p_h[2], p_l[2]);
            split2(ds[2*kap+1][2], ds[2*kap+1][3], p_h[3], p_l[3]);
            #pragma unroll
            for (int j16 = 0; j16 < 4; j16++) {
                const uint32_t va = base + AVH + (uint32_t)(kap * 2048) + vrow +
                                    (uint32_t)((((j16 << 1) | vchk) ^ vsw) << 4);
                uint32_t vhf[4], vlf[4];
                ldm_x4_t(vhf, va);
                ldm_x4_t(vlf, va + 16384);
                uint32_t v0h[2] = {vhf[0], vhf[1]}, v1h[2] = {vhf[2], vhf[3]};
                uint32_t v0l[2] = {vlf[0], vlf[1]}, v1l[2] = {vlf[2], vlf[3]};
                mma_bf16(d_y[2*j16],   p_h, v0h);
                mma_bf16(d_y[2*j16],   p_h, v0l);
                mma_bf16(d_y[2*j16],   p_l, v0h);
                mma_bf16(d_y[2*j16+1], p_h, v1h);
                mma_bf16(d_y[2*j16+1], p_h, v1l);
                mma_bf16(d_y[2*j16+1], p_l, v1h);
            }
        }
        __syncthreads();
    }

    // finalize: row sums, write y as bf16 hi/lo
    lsum0 += __shfl_xor_sync(0xffffffffu, lsum0, 1);
    lsum0 += __shfl_xor_sync(0xffffffffu, lsum0, 2);
    lsum1 += __shfl_xor_sync(0xffffffffu, lsum1, 1);
    lsum1 += __shfl_xor_sync(0xffffffffu, lsum1, 2);
    const float inv0 = 1.f / lsum0;
    const float inv1 = 1.f / lsum1;
    if ((lane & 3) == 0) {
        g_lsum[(size_t)bh * Tn + qbase + rl0]     = lsum0;
        g_lsum[(size_t)bh * Tn + qbase + rl0 + 8] = lsum1;
    }
    const int b = bh >> 4, hh = bh & 15;
    const size_t y0i = ((size_t)(b * Tn + qbase + rl0)) * Cn + hh * 64;
    const size_t y1i = y0i + (size_t)8 * Cn;
    #pragma unroll
    for (int j = 0; j < 8; j++) {
        uint32_t h, l;
        split2(d_y[j][0] * inv0, d_y[j][1] * inv0, h, l);
        *(uint32_t*)(g_yh + y0i + 8 * j + cl0) = h;
        *(uint32_t*)(g_yl + y0i + 8 * j + cl0) = l;
        split2(d_y[j][2] * inv1, d_y[j][3] * inv1, h, l);
        *(uint32_t*)(g_yh + y1i + 8 * j + cl0) = h;
        *(uint32_t*)(g_yl + y1i + 8 * j + cl0) = l;
    }
}

// ---------------------------------------------------------------------------
// Normalize att rows by 1/l. Warp per row. Triggers programmatic launch of
// the dependent proj GEMM immediately (proj does not read att/g_lsum).
// ---------------------------------------------------------------------------
__global__ __launch_bounds__(256) void norm_att(float* __restrict__ att)
{
    cudaTriggerProgrammaticLaunchCompletion();
    const int wid = threadIdx.x >> 5, lane = threadIdx.x & 31;
    const size_t row = (size_t)blockIdx.x * 8 + wid;
    const int rs = (int)(row & (Tn - 1));
    const int width = ((rs >> 7) + 1) * 128;
    const float inv = 1.f / g_lsum[row];
    float* p = att + row * Tn;
    for (int c = lane * 4; c < width; c += 128) {
        float4 v = *(float4*)(p + c);
        v.x *= inv; v.y *= inv; v.z *= inv; v.w *= inv;
        *(float4*)(p + c) = v;
    }
}

// ---------------------------------------------------------------------------
extern "C" void kernel_launch(void* const* d_in, const int* in_sizes, int n_in,
                              void* d_out, int out_size)
{
    const float* x  = (const float*)d_in[0];
    const float* Wq = (const float*)d_in[1];
    const float* bq = (const float*)d_in[2];
    const float* Wk = (const float*)d_in[3];
    const float* bk = (const float*)d_in[4];
    const float* Wv = (const float*)d_in[5];
    const float* bv = (const float*)d_in[6];
    const float* Wp = (const float*)d_in[7];
    const float* bp = (const float*)d_in[8];

    float* y_out   = (float*)d_out;                       // [B,T,C]
    float* att_out = y_out + (size_t)BT * Cn;             // [B,H,T,T]

    cudaFuncSetAttribute(gemm_qkv_tc,  cudaFuncAttributeMaxDynamicSharedMemorySize, GEMM_SMEM);
    cudaFuncSetAttribute(gemm_proj_tc, cudaFuncAttributeMaxDynamicSharedMemorySize, GEMM_SMEM);
    cudaFuncSetAttribute(attn_mma,     cudaFuncAttributeMaxDynamicSharedMemorySize, ATT_SMEM);

    // pre-split x and weights to bf16 hi/lo (one kernel)
    conv_all<<<8192 + 4096, 256>>>((const float4*)x, (const float4*)Wq,
                                   (const float4*)Wk, (const float4*)Wv,
                                   (const float4*)Wp);

    // QKV projections -> bf16 hi/lo q,k,v (q pre-scaled 1/8)
    gemm_qkv_tc<<<dim3(8, 64, 3), 256, GEMM_SMEM>>>(bq, bk, bv);

    // Fused MMA attention: unnormalized E -> att, row sums, y = E@V / l
    attn_mma<<<dim3(NQT, Bn * Hn), 256, ATT_SMEM>>>(att_out);

    // Normalize att lower triangle by 1/l (triggers PDL for proj)
    norm_att<<<(64 * Tn) / 8, 256>>>(att_out);

    // Output projection — overlaps with norm_att via programmatic dependent
    // launch (proj's inputs g_yh/g_yl/weights are ready after attn_mma).
    {
        cudaLaunchConfig_t cfg = {};
        cfg.gridDim = dim3(8, 64);
        cfg.blockDim = dim3(256);
        cfg.dynamicSmemBytes = GEMM_SMEM;
        cfg.stream = 0;
        cudaLaunchAttribute attrs[1];
        attrs[0].id = cudaLaunchAttributeProgrammaticStreamSerialization;
        attrs[0].val.programmaticStreamSerializationAllowed = 1;
        cfg.attrs = attrs;
        cfg.numAttrs = 1;
        cudaLaunchKernelEx(&cfg, gemm_proj_tc, bp, y_out);
    }
}

// round 15
// speedup vs baseline: 1.6847x; 1.0264x over previous
#include <cuda_runtime.h>
#include <cuda_bf16.h>
#include <math_constants.h>
#include <cstdint>

#define Bn 4
#define Tn 2048
#define Cn 1024
#define Hn 16
#define Dn 64
#define BT (Bn*Tn)      // 8192
#define NQT (Tn/128)    // 16 q-tiles of 128

typedef unsigned short ushort_t;

// Scratch (device globals — no allocation allowed)
__device__ __align__(16) ushort_t g_qh[(size_t)64*Tn*Dn];   // bf16 hi/lo of q (pre-scaled 0.125)
__device__ __align__(16) ushort_t g_ql[(size_t)64*Tn*Dn];
__device__ __align__(16) ushort_t g_kh[(size_t)64*Tn*Dn];
__device__ __align__(16) ushort_t g_kl[(size_t)64*Tn*Dn];
__device__ __align__(16) ushort_t g_vh[(size_t)64*Tn*Dn];
__device__ __align__(16) ushort_t g_vl[(size_t)64*Tn*Dn];
__device__ __align__(16) ushort_t g_xh[(size_t)BT*Cn];      // x pre-split
__device__ __align__(16) ushort_t g_xl[(size_t)BT*Cn];
__device__ __align__(16) ushort_t g_wh[(size_t)4*Cn*Cn];    // Wq,Wk,Wv,Wp pre-split
__device__ __align__(16) ushort_t g_wl[(size_t)4*Cn*Cn];
__device__ __align__(16) ushort_t g_yh[(size_t)BT*Cn];      // attention out (normalized), pre-split
__device__ __align__(16) ushort_t g_yl[(size_t)BT*Cn];
__device__ float g_lsum[(size_t)64*Tn];                     // softmax row sums (131072 rows)

// ---------------------------------------------------------------------------
// helpers
// ---------------------------------------------------------------------------
__device__ __forceinline__ uint32_t smem_u32(const void* p) {
    uint32_t a;
    asm("{ .reg .u64 t; cvta.to.shared.u64 t, %1; cvt.u32.u64 %0, t; }"
        : "=r"(a) : "l"(p));
    return a;
}

__device__ __forceinline__ void split2(float f0, float f1, uint32_t& hi, uint32_t& lo) {
    __nv_bfloat16 h0 = __float2bfloat16(f0);
    __nv_bfloat16 h1 = __float2bfloat16(f1);
    __nv_bfloat16 l0 = __float2bfloat16(f0 - __bfloat162float(h0));
    __nv_bfloat16 l1 = __float2bfloat16(f1 - __bfloat162float(h1));
    hi = (uint32_t)__bfloat16_as_ushort(h0) | ((uint32_t)__bfloat16_as_ushort(h1) << 16);
    lo = (uint32_t)__bfloat16_as_ushort(l0) | ((uint32_t)__bfloat16_as_ushort(l1) << 16);
}

__device__ __forceinline__ void ldm_x4(uint32_t r[4], uint32_t addr) {
    asm volatile("ldmatrix.sync.aligned.m8n8.x4.shared.b16 {%0,%1,%2,%3}, [%4];"
        : "=r"(r[0]), "=r"(r[1]), "=r"(r[2]), "=r"(r[3]) : "r"(addr));
}

__device__ __forceinline__ void ldm_x4_t(uint32_t r[4], uint32_t addr) {
    asm volatile("ldmatrix.sync.aligned.m8n8.x4.trans.shared.b16 {%0,%1,%2,%3}, [%4];"
        : "=r"(r[0]), "=r"(r[1]), "=r"(r[2]), "=r"(r[3]) : "r"(addr));
}

__device__ __forceinline__ void mma_bf16(float d[4], const uint32_t a[4], const uint32_t b[2]) {
    asm volatile(
        "mma.sync.aligned.m16n8k16.row.col.f32.bf16.bf16.f32 "
        "{%0,%1,%2,%3}, {%4,%5,%6,%7}, {%8,%9}, {%0,%1,%2,%3};"
        : "+f"(d[0]), "+f"(d[1]), "+f"(d[2]), "+f"(d[3])
        : "r"(a[0]), "r"(a[1]), "r"(a[2]), "r"(a[3]), "r"(b[0]), "r"(b[1]));
}

#define CP16(dst, src) asm volatile("cp.async.cg.shared.global [%0], [%1], 16;" :: "r"(dst), "l"(src))
#define CPCOMMIT()     asm volatile("cp.async.commit_group;" ::: "memory")
#define CPWAIT0()      asm volatile("cp.async.wait_group 0;" ::: "memory")
#define CPWAIT1()      asm volatile("cp.async.wait_group 1;" ::: "memory")

// ---------------------------------------------------------------------------
// combined pre-convert kernel: fp32 -> bf16 hi/lo for x and all 4 weights
// ---------------------------------------------------------------------------
__global__ __launch_bounds__(256) void conv_all(
    const float4* __restrict__ x,
    const float4* __restrict__ Wq, const float4* __restrict__ Wk,
    const float4* __restrict__ Wv, const float4* __restrict__ Wp)
{
    int b = blockIdx.x;
    const float4* src;
    uint2 *dh, *dl;
    int i;
    if (b < 8192) {               // x: 2M float4
        i = b * 256 + threadIdx.x;
        src = x; dh = (uint2*)g_xh; dl = (uint2*)g_xl;
    } else {                      // weights: 4 x 256K float4
        b -= 8192;
        const int z = b >> 10;
        src = (z == 0) ? Wq : (z == 1) ? Wk : (z == 2) ? Wv : Wp;
        dh = (uint2*)(g_wh + (size_t)z * Cn * Cn);
        dl = (uint2*)(g_wl + (size_t)z * Cn * Cn);
        i = (b & 1023) * 256 + threadIdx.x;
    }
    float4 v = src[i];
    uint32_t h0, l0, h1, l1;
    split2(v.x, v.y, h0, l0);
    split2(v.z, v.w, h1, l1);
    dh[i] = make_uint2(h0, h1);
    dl[i] = make_uint2(l0, l1);
}

// ===========================================================================
// bf16 pre-split GEMM, cp.async 3-stage, CTA 128x128, warp tile 64x32
// (8 warps: 2m x 4n), ~120 regs -> 2 CTAs/SM.  (R8, unchanged)
// ===========================================================================
#define GSTG 37888
#define GEMM_SMEM (3*GSTG)   // 113664

__device__ __forceinline__ void gemm_issue(
    uint32_t sbase,
    const ushort_t* __restrict__ Ah_g, const ushort_t* __restrict__ Al_g,
    const ushort_t* __restrict__ Bh_g, const ushort_t* __restrict__ Bl_g,
    int bm, int bn, int kc, int tid)
{
    #pragma unroll
    for (int i = 0; i < 2; i++) {
        const int ia = tid + 256 * i;
        const int r = ia >> 2, c = ia & 3;
        const uint32_t dst = sbase + (uint32_t)(r * 80 + c * 16);
        const size_t src = (size_t)(bm * 128 + r) * 1024 + kc * 32 + c * 8;
        CP16(dst, Ah_g + src);
        CP16(dst + 10240, Al_g + src);
    }
    #pragma unroll
    for (int i = 0; i < 2; i++) {
        const int ib = tid + 256 * i;
        const int k = ib >> 4, c = ib & 15;
        const uint32_t dst = sbase + (uint32_t)(20480 + k * 272 + c * 16);
        const size_t src = (size_t)(kc * 32 + k) * 1024 + bn * 128 + c * 8;
        CP16(dst, Bh_g + src);
        CP16(dst + 8704, Bl_g + src);
    }
    CPCOMMIT();
}

template<bool REMAP>
__device__ __forceinline__ void gemm2_body(
    const ushort_t* __restrict__ Ah_g, const ushort_t* __restrict__ Al_g,
    const ushort_t* __restrict__ Bh_g, const ushort_t* __restrict__ Bl_g,
    const float* __restrict__ bias, float* __restrict__ out,
    ushort_t* __restrict__ outH, ushort_t* __restrict__ outL, float scl)
{
    extern __shared__ char smc[];
    const uint32_t sb = smem_u32(smc);
    const int tid = threadIdx.x, wid = tid >> 5, lane = tid & 31;
    const int bm = blockIdx.y, bn = blockIdx.x;
    const int warp_m = wid & 1;        // 64 rows each
    const int warp_n = wid >> 1;       // 32 cols each

    const int l15 = lane & 15;
    const int lhi = lane >> 4;
    const uint32_t aBase = sb + (uint32_t)((warp_m * 64 + l15) * 80 + lhi * 16);
    const uint32_t bBase = sb + 20480 + (uint32_t)(l15 * 272 + warp_n * 64 + lhi * 16);

    float d[4][4][4];
    #pragma unroll
    for (int t = 0; t < 4; t++)
        #pragma unroll
        for (int u = 0; u < 4; u++)
            #pragma unroll
            for (int v = 0; v < 4; v++) d[t][u][v] = 0.f;

    gemm_issue(sb,        Ah_g, Al_g, Bh_g, Bl_g, bm, bn, 0, tid);
    gemm_issue(sb + GSTG, Ah_g, Al_g, Bh_g, Bl_g, bm, bn, 1, tid);

    for (int kc = 0; kc < 32; kc++) {
        if (kc == 31) { CPWAIT0(); } else { CPWAIT1(); }
        __syncthreads();
        if (kc < 30)
            gemm_issue(sb + (uint32_t)(((kc + 2) % 3) * GSTG),
                       Ah_g, Al_g, Bh_g, Bl_g, bm, bn, kc + 2, tid);

        const uint32_t stgOff = (uint32_t)((kc % 3) * GSTG);

        #pragma unroll
        for (int ss = 0; ss < 2; ss++) {
            uint32_t Bh[4][2], Bl[4][2];
            #pragma unroll
            for (int gp = 0; gp < 2; gp++) {
                const uint32_t ba = bBase + stgOff + (uint32_t)(ss * 16 * 272 + gp * 32);
                uint32_t r[4];
                ldm_x4_t(r, ba);
                Bh[gp*2][0] = r[0]; Bh[gp*2][1] = r[1];
                Bh[gp*2+1][0] = r[2]; Bh[gp*2+1][1] = r[3];
                ldm_x4_t(r, ba + 8704);
                Bl[gp*2][0] = r[0]; Bl[gp*2][1] = r[1];
                Bl[gp*2+1][0] = r[2]; Bl[gp*2+1][1] = r[3];
            }
            #pragma unroll
            for (int t = 0; t < 4; t++) {
                uint32_t Ah[4], Al_[4];
                const uint32_t aa = aBase + stgOff + (uint32_t)(t * 16 * 80 + ss * 32);
                ldm_x4(Ah, aa);
                ldm_x4(Al_, aa + 10240);
                #pragma unroll
                for (int u = 0; u < 4; u++) {
                    mma_bf16(d[t][u], Ah, Bh[u]);
                    mma_bf16(d[t][u], Ah, Bl[u]);
                    mma_bf16(d[t][u], Al_, Bh[u]);
                }
            }
        }
    }

    // ---- epilogue ----
    #pragma unroll
    for (int t = 0; t < 4; t++) {
        const int rowA = bm * 128 + warp_m * 64 + t * 16 + (lane >> 2);
        #pragma unroll
        for (int half = 0; half < 2; half++) {
            const int m = rowA + half * 8;
            #pragma unroll
            for (int u = 0; u < 4; u++) {
                const int col = bn * 128 + warp_n * 32 + u * 8 + ((lane & 3) << 1);
                const float v0 = d[t][u][half * 2 + 0] + __ldg(&bias[col]);
                const float v1 = d[t][u][half * 2 + 1] + __ldg(&bias[col + 1]);
                if (REMAP) {
                    const int b = m >> 11, tt = m & 2047;
                    const int h = col >> 6, d0 = col & 63;
                    const size_t idx = (((size_t)(b * Hn + h) * Tn) + tt) * Dn + d0;
                    uint32_t hh, ll;
                    split2(v0 * scl, v1 * scl, hh, ll);
                    *(uint32_t*)(outH + idx) = hh;
                    *(uint32_t*)(outL + idx) = ll;
                } else {
                    *(float2*)(out + (size_t)m * 1024 + col) = make_float2(v0, v1);
                }
            }
        }
    }
}

__global__ __launch_bounds__(256, 2) void gemm_qkv_tc(
    const float* __restrict__ bq, const float* __restrict__ bk,
    const float* __restrict__ bv)
{
    const float* bias; ushort_t *oh, *ol; float scl;
    if (blockIdx.z == 0)      { bias = bq; oh = g_qh; ol = g_ql; scl = 0.125f; }
    else if (blockIdx.z == 1) { bias = bk; oh = g_kh; ol = g_kl; scl = 1.f; }
    else                      { bias = bv; oh = g_vh; ol = g_vl; scl = 1.f; }
    const size_t wo = (size_t)blockIdx.z * Cn * Cn;
    gemm2_body<true>(g_xh, g_xl, g_wh + wo, g_wl + wo, bias, nullptr, oh, ol, scl);
}

// proj triggers the dependent norm launch at entry: norm reads only att and
// g_lsum (written by attn_mma, which fully completed before proj launched),
// so norm may run concurrently with proj from its very first cycle.
__global__ __launch_bounds__(256, 2) void gemm_proj_tc(
    const float* __restrict__ bp, float* __restrict__ out)
{
    cudaTriggerProgrammaticLaunchCompletion();
    const size_t wo = (size_t)3 * Cn * Cn;
    gemm2_body<false>(g_yh, g_yl, g_wh + wo, g_wl + wo, bp, out, nullptr, nullptr, 1.f);
}

// ===========================================================================
// MMA attention (R8, unchanged): single pass, unnormalized E -> att,
// y = E@V / l written as bf16 hi/lo.
// ===========================================================================
#define ATT_SMEM 131072
#define AKH 0
#define AKL 16384
#define AVH 32768
#define AVL 49152

__global__ __launch_bounds__(256, 1) void attn_mma(float* __restrict__ att)
{
    extern __shared__ char smc[];
    const uint32_t sb = smem_u32(smc);
    const int tid = threadIdx.x, wid = tid >> 5, lane = tid & 31;
    const int bh = blockIdx.y;
    const int qt = (NQT - 1) - blockIdx.x;
    const int qbase = qt * 128;
    const int nkt = qt + 1;

    const ushort_t* qh = g_qh + ((size_t)bh * Tn + qbase) * Dn;
    const ushort_t* ql = g_ql + ((size_t)bh * Tn + qbase) * Dn;
    const ushort_t* khp = g_kh + (size_t)bh * Tn * Dn;
    const ushort_t* klp = g_kl + (size_t)bh * Tn * Dn;
    const ushort_t* vhp = g_vh + (size_t)bh * Tn * Dn;
    const ushort_t* vlp = g_vl + (size_t)bh * Tn * Dn;
    float* attp = att + ((size_t)bh * Tn + qbase) * Tn;

    // Q stage into buffer0
    #pragma unroll
    for (int i = 0; i < 4; i++) {
        const int idx = tid + 256 * i;
        const int r = idx >> 3, c = idx & 7;
        const uint32_t off = (uint32_t)(r * 128 + ((c ^ (r & 7)) << 4));
        CP16(sb + AKH + off, qh + r * 64 + c * 8);
        CP16(sb + AKL + off, ql + r * 64 + c * 8);
    }
    CPCOMMIT();

    // K/V tile 0 into buffer1
    {
        const uint32_t base = sb + 65536;
        #pragma unroll
        for (int i = 0; i < 4; i++) {
            const int idx = tid + 256 * i;
            const int r = idx >> 3, c = idx & 7;
            const uint32_t off = (uint32_t)(r * 128 + ((c ^ (r & 7)) << 4));
            const size_t so = (size_t)r * 64 + c * 8;
            CP16(base + AKH + off, khp + so);
            CP16(base + AKL + off, klp + so);
            CP16(base + AVH + off, vhp + so);
            CP16(base + AVL + off, vlp + so);
        }
        CPCOMMIT();
    }

    // zero-fill strict-upper tiles while the async loads fly
    const int zstart = nkt * 128;
    #pragma unroll 1
    for (int rg = 0; rg < 16; rg++) {
        const int r = rg * 8 + wid;
        for (int c = zstart + lane * 4; c < Tn; c += 128)
            *(float4*)(attp + (size_t)r * Tn + c) = make_float4(0.f, 0.f, 0.f, 0.f);
    }

    CPWAIT1();
    __syncthreads();

    uint32_t q_h[4][4], q_l[4][4];
    {
        const int arow = 16 * wid + ((lane >> 3) & 1) * 8 + (lane & 7);
        #pragma unroll
        for (int kk = 0; kk < 4; kk++) {
            const uint32_t addr = sb + AKH + (uint32_t)(arow * 128 +
                (((2 * kk + (lane >> 4)) ^ (arow & 7)) << 4));
            ldm_x4(q_h[kk], addr);
            ldm_x4(q_l[kk], addr + 16384);
        }
    }
    __syncthreads();

    const int bkeyL = ((lane >> 4) << 3) + (lane & 7);
    const int bchk  = (lane >> 3) & 1;
    const uint32_t brow = (uint32_t)(bkeyL * 128);
    const int bsw = bkeyL & 7;

    const int vkeyL = ((lane >> 3) & 1) * 8 + (lane & 7);
    const int vchk  = lane >> 4;
    const uint32_t vrow = (uint32_t)(vkeyL * 128);
    const int vsw = vkeyL & 7;

    const int rl0 = 16 * wid + (lane >> 2);
    const int cl0 = 2 * (lane & 3);

    float d_y[8][4];
    #pragma unroll
    for (int j = 0; j < 8; j++)
        #pragma unroll
        for (int v = 0; v < 4; v++) d_y[j][v] = 0.f;
    float lsum0 = 0.f, lsum1 = 0.f;

    for (int kt = 0; kt < nkt; kt++) {
        const int buf = (kt + 1) & 1;
        if (kt + 1 < nkt) {
            const uint32_t base = sb + (uint32_t)((kt & 1) * 65536);
            const size_t tof = (size_t)(kt + 1) * 128 * 64;
            #pragma unroll
            for (int i = 0; i < 4; i++) {
                const int idx = tid + 256 * i;
                const int r = idx >> 3, c = idx & 7;
                const uint32_t off = (uint32_t)(r * 128 + ((c ^ (r & 7)) << 4));
                const size_t so = tof + (size_t)r * 64 + c * 8;
                CP16(base + AKH + off, khp + so);
                CP16(base + AKL + off, klp + so);
                CP16(base + AVH + off, vhp + so);
                CP16(base + AVL + off, vlp + so);
            }
            CPCOMMIT();
            CPWAIT1();
        } else {
            CPWAIT0();
        }
        __syncthreads();

        const uint32_t base = sb + (uint32_t)(buf * 65536);

        float ds[16][4];
        #pragma unroll
        for (int j = 0; j < 16; j++)
            #pragma unroll
            for (int v = 0; v < 4; v++) ds[j][v] = 0.f;

        #pragma unroll
        for (int kk = 0; kk < 4; kk++) {
            #pragma unroll
            for (int j16 = 0; j16 < 8; j16++) {
                const uint32_t ka = base + AKH + (uint32_t)(j16 * 2048) + brow +
                                    (uint32_t)((((kk << 1) | bchk) ^ bsw) << 4);
                uint32_t khf[4], klf[4];
                ldm_x4(khf, ka);
                ldm_x4(klf, ka + 16384);
                uint32_t b0h[2] = {khf[0], khf[1]}, b1h[2] = {khf[2], khf[3]};
                uint32_t b0l[2] = {klf[0], klf[1]}, b1l[2] = {klf[2], klf[3]};
                mma_bf16(ds[2*j16],   q_h[kk], b0h);
                mma_bf16(ds[2*j16],   q_h[kk], b0l);
                mma_bf16(ds[2*j16],   q_l[kk], b0h);
                mma_bf16(ds[2*j16+1], q_h[kk], b1h);
                mma_bf16(ds[2*j16+1], q_h[kk], b1l);
                mma_bf16(ds[2*j16+1], q_l[kk], b1h);
            }
        }

        const bool diag = (kt == qt);
        const int ktbase = kt * 128;
        #pragma unroll
        for (int j = 0; j < 16; j++) {
            const int c = 8 * j + cl0;
            float e00 = __expf(ds[j][0]);
            float e01 = __expf(ds[j][1]);
            float e10 = __expf(ds[j][2]);
            float e11 = __expf(ds[j][3]);
            if (diag) {
                if (c     > rl0)     e00 = 0.f;
                if (c + 1 > rl0)     e01 = 0.f;
                if (c     > rl0 + 8) e10 = 0.f;
                if (c + 1 > rl0 + 8) e11 = 0.f;
            }
            ds[j][0] = e00; ds[j][1] = e01; ds[j][2] = e10; ds[j][3] = e11;
            *(float2*)(attp + (size_t)rl0 * Tn + ktbase + c)       = make_float2(e00, e01);
            *(float2*)(attp + (size_t)(rl0 + 8) * Tn + ktbase + c) = make_float2(e10, e11);
            lsum0 += e00 + e01;
            lsum1 += e10 + e11;
        }

        #pragma unroll
        for (int kap = 0; kap < 8; kap++) {
            uint32_t p_h[4], p_l[4];
            split2(ds[2*kap][0],   ds[2*kap][1],   p_h[0], p_l[0]);
            split2(ds[2*kap][2],   ds[2*kap][3],   p_h[1], p_l[1]);
            split2(ds[2*kap+1][0], ds[2*kap+1][1], p_h[2], p_l[2]);
            split2(ds[2*kap+1][2], ds[2*kap+1][3], p_h[3], p_l[3]);
            #pragma unroll
            for (int j16 = 0; j16 < 4; j16++) {
                const uint32_t va = base + AVH + (uint32_t)(kap * 2048) + vrow +
                                    (uint32_t)((((j16 << 1) | vchk) ^ vsw) << 4);
                uint32_t vhf[4], vlf[4];
                ldm_x4_t(vhf, va);
                ldm_x4_t(vlf, va + 16384);
                uint32_t v0h[2] = {vhf[0], vhf[1]}, v1h[2] = {vhf[2], vhf[3]};
                uint32_t v0l[2] = {vlf[0], vlf[1]}, v1l[2] = {vlf[2], vlf[3]};
                mma_bf16(d_y[2*j16],   p_h, v0h);
                mma_bf16(d_y[2*j16],   p_h, v0l);
                mma_bf16(d_y[2*j16],   p_l, v0h);
                mma_bf16(d_y[2*j16+1], p_h, v1h);
                mma_bf16(d_y[2*j16+1], p_h, v1l);
                mma_bf16(d_y[2*j16+1], p_l, v1h);
            }
        }
        __syncthreads();
    }

    // finalize: row sums, write y as bf16 hi/lo
    lsum0 += __shfl_xor_sync(0xffffffffu, lsum0, 1);
    lsum0 += __shfl_xor_sync(0xffffffffu, lsum0, 2);
    lsum1 += __shfl_xor_sync(0xffffffffu, lsum1, 1);
    lsum1 += __shfl_xor_sync(0xffffffffu, lsum1, 2);
    const float inv0 = 1.f / lsum0;
    const float inv1 = 1.f / lsum1;
    if ((lane & 3) == 0) {
        g_lsum[(size_t)bh * Tn + qbase + rl0]     = lsum0;
        g_lsum[(size_t)bh * Tn + qbase + rl0 + 8] = lsum1;
    }
    const int b = bh >> 4, hh = bh & 15;
    const size_t y0i = ((size_t)(b * Tn + qbase + rl0)) * Cn + hh * 64;
    const size_t y1i = y0i + (size_t)8 * Cn;
    #pragma unroll
    for (int j = 0; j < 8; j++) {
        uint32_t h, l;
        split2(d_y[j][0] * inv0, d_y[j][1] * inv0, h, l);
        *(uint32_t*)(g_yh + y0i + 8 * j + cl0) = h;
        *(uint32_t*)(g_yl + y0i + 8 * j + cl0) = l;
        split2(d_y[j][2] * inv1, d_y[j][3] * inv1, h, l);
        *(uint32_t*)(g_yh + y1i + 8 * j + cl0) = h;
        *(uint32_t*)(g_yl + y1i + 8 * j + cl0) = l;
    }
}

// ---------------------------------------------------------------------------
// Normalize att rows by 1/l. Warp per row. Launched with PSS so it starts
// as soon as proj's CTAs trigger (data deps satisfied by attn_mma already).
// ---------------------------------------------------------------------------
__global__ __launch_bounds__(256) void norm_att(float* __restrict__ att)
{
    const int wid = threadIdx.x >> 5, lane = threadIdx.x & 31;
    const size_t row = (size_t)blockIdx.x * 8 + wid;
    const int rs = (int)(row & (Tn - 1));
    const int width = ((rs >> 7) + 1) * 128;
    const float inv = 1.f / g_lsum[row];
    float* p = att + row * Tn;
    for (int c = lane * 4; c < width; c += 128) {
        float4 v = *(float4*)(p + c);
        v.x *= inv; v.y *= inv; v.z *= inv; v.w *= inv;
        *(float4*)(p + c) = v;
    }
}

// ---------------------------------------------------------------------------
extern "C" void kernel_launch(void* const* d_in, const int* in_sizes, int n_in,
                              void* d_out, int out_size)
{
    const float* x  = (const float*)d_in[0];
    const float* Wq = (const float*)d_in[1];
    const float* bq = (const float*)d_in[2];
    const float* Wk = (const float*)d_in[3];
    const float* bk = (const float*)d_in[4];
    const float* Wv = (const float*)d_in[5];
    const float* bv = (const float*)d_in[6];
    const float* Wp = (const float*)d_in[7];
    const float* bp = (const float*)d_in[8];

    float* y_out   = (float*)d_out;                       // [B,T,C]
    float* att_out = y_out + (size_t)BT * Cn;             // [B,H,T,T]

    cudaFuncSetAttribute(gemm_qkv_tc,  cudaFuncAttributeMaxDynamicSharedMemorySize, GEMM_SMEM);
    cudaFuncSetAttribute(gemm_proj_tc, cudaFuncAttributeMaxDynamicSharedMemorySize, GEMM_SMEM);
    cudaFuncSetAttribute(attn_mma,     cudaFuncAttributeMaxDynamicSharedMemorySize, ATT_SMEM);

    // pre-split x and weights to bf16 hi/lo (one kernel)
    conv_all<<<8192 + 4096, 256>>>((const float4*)x, (const float4*)Wq,
                                   (const float4*)Wk, (const float4*)Wv,
                                   (const float4*)Wp);

    // QKV projections -> bf16 hi/lo q,k,v (q pre-scaled 1/8)
    gemm_qkv_tc<<<dim3(8, 64, 3), 256, GEMM_SMEM>>>(bq, bk, bv);

    // Fused MMA attention: unnormalized E -> att, row sums, y = E@V / l
    attn_mma<<<dim3(NQT, Bn * Hn), 256, ATT_SMEM>>>(att_out);

    // Output projection (plain launch; triggers PDL for norm at entry)
    gemm_proj_tc<<<dim3(8, 64), 256, GEMM_SMEM>>>(bp, y_out);

    // att normalization — overlaps with proj via programmatic dependent
    // launch (norm's inputs att/g_lsum were finalized by attn_mma).
    {
        cudaLaunchConfig_t cfg = {};
        cfg.gridDim = dim3((64 * Tn) / 8);
        cfg.blockDim = dim3(256);
        cfg.dynamicSmemBytes = 0;
        cfg.stream = 0;
        cudaLaunchAttribute attrs[1];
        attrs[0].id = cudaLaunchAttributeProgrammaticStreamSerialization;
        attrs[0].val.programmaticStreamSerializationAllowed = 1;
        cfg.attrs = attrs;
        cfg.numAttrs = 1;
        cudaLaunchKernelEx(&cfg, norm_att, att_out);
    }
}